// round 14
// baseline (speedup 1.0000x reference)
#include <cuda_runtime.h>
#include <cuda_fp16.h>
#include <math.h>
#include <stdint.h>

// ---------------- problem constants ----------------
#define BB 4
#define SS 1024
#define DD 1024
#define NQ 8
#define BSROWS (BB*SS)           // 4096
#define CLS_SCALE (0.7f/128.0f)  // ALPHA / (H*sqrt(HEAD_DIM))

#define NM (BSROWS*DD)           // 4,194,304
#define NW (DD*DD)               // 1,048,576

// ---------------- scratch (device globals) ----------------
__device__ uint4 g_qh[NM/8], g_kh[NM/8], g_vh[NM/8];
__device__ uint4 g_wT[3][NW/8];              // WqT, WkT, WvT (fp16, transposed)
__device__ uint4 g_woh[NW/8];                // Wo fp16 (row-major)
__device__ uint4 g_W1T[NW/8], g_G[NW/8];     // composed weights fp16
__device__ uint4 g_Th[NM/8], g_VO[NM/8], g_VOT[NM/8], g_Ph[NM/8];
__device__ float g_SC[NM];                   // unnormalized p (fp32)
__device__ float g_Sa[BSROWS], g_Ta[BSROWS], g_Sb[BSROWS], g_Tb[BSROWS];
__device__ float g_cpart[32*DD];
__device__ float g_cvec[DD];
__device__ float g_gw[BSROWS];
__device__ float g_obias[DD];
__device__ float g_rsum[BSROWS];             // 1 / row sum of p

// ---------------- lookup tables ----------------
#define TBL_N   4096
#define TBL_Z0  5.5f
#define TBL_Z1  44.0f
#define TBL_E0f (-16.0f)
#define TBL_E1f (16.0f)
__device__ float4 g_tblZ[TBL_N];   // (ln, dln, rcp, drcp)
__device__ float2 g_tblE[TBL_N];   // (exp, dexp)

__global__ void build_tables_kernel()
{
    int k = blockIdx.x * blockDim.x + threadIdx.x;
    if (k >= TBL_N) return;
    const float hz = (TBL_Z1 - TBL_Z0) / TBL_N;
    float z0 = TBL_Z0 + k * hz, z1 = z0 + hz;
    float l0 = logf(z0), l1 = logf(z1);
    float r0 = 1.0f / z0,  r1 = 1.0f / z1;
    g_tblZ[k] = make_float4(l0, (l1 - l0) / hz, r0, (r1 - r0) / hz);
    const float he = (TBL_E1f - TBL_E0f) / TBL_N;
    float x0 = TBL_E0f + k * he, x1 = x0 + he;
    float e0 = expf(x0), e1 = expf(x1);
    g_tblE[k] = make_float2(e0, (e1 - e0) / he);
}

// ---------------- PTX helpers ----------------
__device__ __forceinline__ uint32_t smem_u32(const void* p) {
    uint32_t a;
    asm("{ .reg .u64 t; cvta.to.shared.u64 t, %1; cvt.u32.u64 %0, t; }" : "=r"(a) : "l"(p));
    return a;
}
__device__ __forceinline__ void cp16(uint32_t dst, const void* src) {
    asm volatile("cp.async.cg.shared.global [%0], [%1], 16;" :: "r"(dst), "l"(src) : "memory");
}
__device__ __forceinline__ void cp_commit() { asm volatile("cp.async.commit_group;" ::: "memory"); }
template<int N>
__device__ __forceinline__ void cp_wait() { asm volatile("cp.async.wait_group %0;" :: "n"(N) : "memory"); }

__device__ __forceinline__ void ldsm4(uint32_t& r0, uint32_t& r1, uint32_t& r2, uint32_t& r3,
                                      uint32_t addr) {
    asm volatile("ldmatrix.sync.aligned.m8n8.x4.shared.b16 {%0,%1,%2,%3}, [%4];"
                 : "=r"(r0), "=r"(r1), "=r"(r2), "=r"(r3) : "r"(addr));
}
__device__ __forceinline__ void mma16816(float* c, const uint32_t* a, const uint32_t* b) {
    asm volatile("mma.sync.aligned.m16n8k16.row.col.f32.f16.f16.f32 "
                 "{%0,%1,%2,%3}, {%4,%5,%6,%7}, {%8,%9}, {%0,%1,%2,%3};"
                 : "+f"(c[0]), "+f"(c[1]), "+f"(c[2]), "+f"(c[3])
                 : "r"(a[0]), "r"(a[1]), "r"(a[2]), "r"(a[3]), "r"(b[0]), "r"(b[1]));
}

// quantum + exp (table-driven)
__device__ __forceinline__ float quantum_exp(float x, float Sa_, float Ta_,
                                             float Sb_, float Tb_, float gw_)
{
    const float HZ = (TBL_Z1 - TBL_Z0) / TBL_N;
    const float INV_HZ = (float)TBL_N / (TBL_Z1 - TBL_Z0);
    const float HE = (TBL_E1f - TBL_E0f) / TBL_N;
    const float INV_HE = (float)TBL_N / (TBL_E1f - TBL_E0f);
    float Z = Sa_ + Sb_;
    float tz = (Z - TBL_Z0) * INV_HZ;
    int kk = (int)tz;
    float4 c4 = __ldg(&g_tblZ[kk]);
    float fz = (Z - TBL_Z0) - HZ * (float)kk;
    float lnZ = fmaf(c4.y, fz, c4.x);
    float rz  = fmaf(c4.w, fz, c4.z);
    float c = x + gw_ + 0.3f * (lnZ - (Ta_ + Tb_) * rz);
    float tx = (c - TBL_E0f) * INV_HE;
    tx = fminf(fmaxf(tx, 0.f), (float)(TBL_N - 1));
    int ke = (int)tx;
    float2 e2 = __ldg(&g_tblE[ke]);
    float fe = (c - TBL_E0f) - HE * (float)ke;
    return fmaf(e2.y, fe, e2.x);
}

// ---------------- fp16 HMMA GEMM core (templated epilogue) ----------------
#define BM 128
#define BN 128
#define BKK 64
#define NT_THREADS 256
#define OFF_B 16384
#define STAGE_BYTES 32768
#define NSTAGE 3
#define SMEM_GEMM (NSTAGE*STAGE_BYTES)

__device__ __forceinline__ void load_stage(
    uint32_t st, const __half* a, const __half* b, int K, int k0, int tid)
{
    #pragma unroll
    for (int i = 0; i < 4; i++) {
        int id = tid + i * 256;
        int r = id >> 3, c = id & 7;
        uint32_t off = (uint32_t)(r * 128 + ((c ^ (r & 7)) << 4));
        size_t ge = (size_t)r * K + k0 + c * 8;
        cp16(st + off,         a + ge);
        cp16(st + OFF_B + off, b + ge);
    }
}

template<int EPI>
__device__ __forceinline__ void gemm_core(
    const __half* __restrict__ a_p, const __half* __restrict__ b_p,
    float* __restrict__ Cf, __half* __restrict__ Ch,
    const float* __restrict__ bias, float scale, int K, int ldc,
    int row_base, int col_base, char* smem,
    const float* qSa, const float* qTa, const float* qSb, const float* qTb,
    const float* qgw, float* Pf, const float* rs)
{
    const uint32_t sbase = smem_u32(smem);
    const int tid  = threadIdx.x;
    const int lane = tid & 31;
    const int wid  = tid >> 5;
    const int warp_m = wid >> 2;
    const int warp_n = wid & 3;
    const int g = lane >> 3;
    const int r = lane & 7;

    float acc[4][4][4];
    #pragma unroll
    for (int i = 0; i < 4; i++)
        #pragma unroll
        for (int j = 0; j < 4; j++)
            #pragma unroll
            for (int q = 0; q < 4; q++) acc[i][j][q] = 0.f;

    const int NKB = K / BKK;

    load_stage(sbase, a_p, b_p, K, 0, tid);
    cp_commit();
    load_stage(sbase + STAGE_BYTES, a_p, b_p, K, BKK, tid);
    cp_commit();

    int sidx = 0;
    for (int kb = 0; kb < NKB; kb++) {
        if (kb + 1 < NKB) cp_wait<1>(); else cp_wait<0>();
        __syncthreads();

        if (kb + 2 < NKB) {
            int s2 = sidx + 2; if (s2 >= NSTAGE) s2 -= NSTAGE;
            load_stage(sbase + s2 * STAGE_BYTES, a_p, b_p, K, (kb + 2) * BKK, tid);
            cp_commit();
        }

        const uint32_t st = sbase + sidx * STAGE_BYTES;
        #pragma unroll
        for (int ks = 0; ks < 4; ks++) {
            uint32_t ah[4][4], bh[4][2];
            const int cA = ((2 * ks + (g >> 1)) ^ r) << 4;
            #pragma unroll
            for (int mi = 0; mi < 4; mi++) {
                uint32_t rowA = warp_m * 64 + mi * 16 + ((g & 1) << 3) + r;
                ldsm4(ah[mi][0], ah[mi][1], ah[mi][2], ah[mi][3], st + rowA * 128 + cA);
            }
            const int cB = ((2 * ks + (g & 1)) ^ r) << 4;
            #pragma unroll
            for (int p = 0; p < 2; p++) {
                uint32_t rowB = warp_n * 32 + ((2 * p + (g >> 1)) << 3) + r;
                uint32_t t0, t1, t2, t3;
                ldsm4(t0, t1, t2, t3, st + OFF_B + rowB * 128 + cB);
                bh[2*p][0] = t0; bh[2*p][1] = t1; bh[2*p+1][0] = t2; bh[2*p+1][1] = t3;
            }
            #pragma unroll
            for (int mi = 0; mi < 4; mi++)
                #pragma unroll
                for (int ni = 0; ni < 4; ni++)
                    mma16816(acc[mi][ni], ah[mi], bh[ni]);
        }
        sidx++; if (sidx >= NSTAGE) sidx = 0;
    }

    #pragma unroll
    for (int mi = 0; mi < 4; mi++) {
        #pragma unroll
        for (int ni = 0; ni < 4; ni++) {
            const int row0 = row_base + warp_m * 64 + mi * 16 + (lane >> 2);
            const int col  = col_base + warp_n * 32 + ni * 8 + 2 * (lane & 3);
            #pragma unroll
            for (int h = 0; h < 2; h++) {
                float x0 = acc[mi][ni][2*h + 0] * scale;
                float x1 = acc[mi][ni][2*h + 1] * scale;
                const int row = row0 + 8*h;
                const size_t o = (size_t)row * ldc + col;
                if (EPI == 0) {
                    union { __half b[2]; uint32_t u; } H;
                    H.b[0] = __float2half(x0); H.b[1] = __float2half(x1);
                    *(uint32_t*)&Ch[o] = H.u;
                } else if (EPI == 1) {
                    float Sa_ = __ldg(qSa + row), Ta_ = __ldg(qTa + row);
                    float p0 = quantum_exp(x0, Sa_, Ta_, __ldg(qSb + col),
                                           __ldg(qTb + col), __ldg(qgw + col));
                    float p1 = quantum_exp(x1, Sa_, Ta_, __ldg(qSb + col + 1),
                                           __ldg(qTb + col + 1), __ldg(qgw + col + 1));
                    *(float2*)&Pf[o] = make_float2(p0, p1);
                    union { __half b[2]; uint32_t u; } H;
                    H.b[0] = __float2half(p0); H.b[1] = __float2half(p1);
                    *(uint32_t*)&Ch[o] = H.u;
                } else {  // EPI == 2
                    float r_ = __ldg(rs + row);
                    float y0 = fmaf(x0, r_, __ldg(bias + col));
                    float y1 = fmaf(x1, r_, __ldg(bias + col + 1));
                    *(float2*)&Cf[o] = make_float2(y0, y1);
                }
            }
        }
    }
}

// dual NT GEMM (EPI0; used for the two small composed-weight GEMMs)
__global__ __launch_bounds__(NT_THREADS, 2)
void tc_gemm_dual(const __half* __restrict__ A0, const __half* __restrict__ B0, __half* __restrict__ C0,
                  const __half* __restrict__ A1, const __half* __restrict__ B1, __half* __restrict__ C1,
                  int K, int ldc)
{
    extern __shared__ char smem[];
    const __half* A = blockIdx.z ? A1 : A0;
    const __half* B = blockIdx.z ? B1 : B0;
    __half*       C = blockIdx.z ? C1 : C0;
    gemm_core<0>(A + (size_t)blockIdx.y * BM * K,
                 B + (size_t)blockIdx.x * BN * K,
                 nullptr, C, nullptr, 1.0f, K, ldc,
                 blockIdx.y * BM, blockIdx.x * BN, smem,
                 nullptr, nullptr, nullptr, nullptr, nullptr, nullptr, nullptr);
}

// single NT GEMM (EPI0; one big job)
__global__ __launch_bounds__(NT_THREADS, 2)
void tc_gemm_one(const __half* __restrict__ A, const __half* __restrict__ B,
                 __half* __restrict__ C, int K, int ldc)
{
    extern __shared__ char smem[];
    gemm_core<0>(A + (size_t)blockIdx.y * BM * K,
                 B + (size_t)blockIdx.x * BN * K,
                 nullptr, C, nullptr, 1.0f, K, ldc,
                 blockIdx.y * BM, blockIdx.x * BN, smem,
                 nullptr, nullptr, nullptr, nullptr, nullptr, nullptr, nullptr);
}

// batched SC GEMM with fused quantum+exp epilogue (EPI1)
__global__ __launch_bounds__(NT_THREADS, 2)
void tc_gemm_sc(const __half* __restrict__ A, const __half* __restrict__ B,
                __half* __restrict__ Ph, float* __restrict__ Pf,
                const float* __restrict__ Sa, const float* __restrict__ Ta,
                const float* __restrict__ Sb, const float* __restrict__ Tb,
                const float* __restrict__ gw)
{
    extern __shared__ char smem[];
    const long z = blockIdx.z;
    gemm_core<1>(A + z * (long)SS * DD + (size_t)blockIdx.y * BM * DD,
                 B + z * (long)SS * DD + (size_t)blockIdx.x * BN * DD,
                 nullptr, Ph + z * (long)SS * SS,
                 nullptr, CLS_SCALE, DD, SS,
                 blockIdx.y * BM, blockIdx.x * BN, smem,
                 Sa + z * SS, Ta + z * SS, Sb + z * SS, Tb + z * SS,
                 gw + z * SS, Pf + z * (long)SS * SS, nullptr);
}

// batched final GEMM with row-scaled output (EPI2)
__global__ __launch_bounds__(NT_THREADS, 2)
void tc_gemm_fin(const __half* __restrict__ A, const __half* __restrict__ B,
                 float* __restrict__ Cf, const float* __restrict__ bias,
                 const float* __restrict__ rs)
{
    extern __shared__ char smem[];
    const long z = blockIdx.z;
    gemm_core<2>(A + z * (long)SS * SS + (size_t)blockIdx.y * BM * SS,
                 B + z * (long)DD * SS + (size_t)blockIdx.x * BN * SS,
                 Cf + z * (long)SS * DD, nullptr,
                 bias, 1.0f, SS, DD,
                 blockIdx.y * BM, blockIdx.x * BN, smem,
                 nullptr, nullptr, nullptr, nullptr, nullptr, nullptr,
                 rs + z * SS);
}

// ---------------- row sums ----------------
__global__ void rowsum_kernel()
{
    const int row  = blockIdx.x * 8 + (threadIdx.x >> 5);
    const int lane = threadIdx.x & 31;
    const float4* pr = (const float4*)(g_SC + (size_t)row * SS);
    float s = 0.f;
    #pragma unroll
    for (int i = 0; i < 8; i++) {
        float4 v = pr[lane + 32 * i];
        s += v.x + v.y + v.z + v.w;
    }
    #pragma unroll
    for (int o = 16; o > 0; o >>= 1) s += __shfl_xor_sync(0xffffffffu, s, o);
    if (lane == 0) g_rsum[row] = 1.0f / s;
}

// ---------------- attn output: attn = p32 * inv ----------------
__global__ __launch_bounds__(256)
void attn_write_kernel(float* __restrict__ attn)
{
    const int row = blockIdx.x;
    const int j0 = threadIdx.x * 4;
    const float inv = g_rsum[row];
    float4 v = *(const float4*)&g_SC[(size_t)row * SS + j0];
    v.x *= inv; v.y *= inv; v.z *= inv; v.w *= inv;
    *(float4*)&attn[(size_t)row * SS + j0] = v;
}

// ---------------- fused q/k/v conversion + row stats ----------------
__global__ __launch_bounds__(256)
void conv_qkv_kernel(const float* __restrict__ q, const float* __restrict__ k,
                     const float* __restrict__ v,
                     __half* __restrict__ qh, __half* __restrict__ kh,
                     __half* __restrict__ vh)
{
    const int which = blockIdx.y;
    const float* src = (which == 0) ? q : (which == 1) ? k : v;
    __half* dst      = (which == 0) ? qh : (which == 1) ? kh : vh;

    int i = (blockIdx.x * blockDim.x + threadIdx.x) * 8;
    float4 v0 = *(const float4*)(src + i);
    float4 v1 = *(const float4*)(src + i + 4);
    float x[8] = {v0.x, v0.y, v0.z, v0.w, v1.x, v1.y, v1.z, v1.w};
    union { uint4 qd; __half b[8]; } H;
    #pragma unroll
    for (int j = 0; j < 8; j++) H.b[j] = __float2half(x[j]);
    *(uint4*)(dst + i) = H.qd;

    if (which < 2 && (i & (DD - 1)) == 0) {
        float s = 0.f, t = 0.f;
        #pragma unroll
        for (int m = 0; m < NQ; m++) {
            float tv = tanhf(x[m]);
            float a = expf(tv);
            s += a; t += a * tv;
        }
        int row = i >> 10;
        if (which == 0) { g_Sa[row] = s; g_Ta[row] = t; }
        else            { g_Sb[row] = s; g_Tb[row] = t; }
    }
}

// ---------------- weight conversion + fused cvec partials ----------------
__global__ void conv_w4_kernel(const float* __restrict__ wq, const float* __restrict__ wk,
                               const float* __restrict__ wv, const float* __restrict__ wo,
                               const float* __restrict__ bq)
{
    const int which = blockIdx.z;
    __shared__ float tile[32][33];
    __shared__ float red[8][32];
    const int tx = threadIdx.x, ty = threadIdx.y;
    if (which < 3) {
        const float* src = (which == 0) ? wq : (which == 1) ? wk : wv;
        __half* dst = (__half*)g_wT[which];
        const int x = blockIdx.x * 32 + tx;
        const int y0 = blockIdx.y * 32;
        #pragma unroll
        for (int i = ty; i < 32; i += 8)
            tile[i][tx] = src[(size_t)(y0 + i) * DD + x];
        __syncthreads();
        #pragma unroll
        for (int i = ty; i < 32; i += 8)
            dst[(size_t)(blockIdx.x * 32 + i) * DD + y0 + tx] = __float2half(tile[tx][i]);
        if (which == 1) {
            float p = 0.f;
            #pragma unroll
            for (int i = 0; i < 4; i++)
                p += bq[y0 + ty * 4 + i] * tile[ty * 4 + i][tx];
            red[ty][tx] = p;
            __syncthreads();
            if (ty == 0) {
                float t = red[0][tx];
                #pragma unroll
                for (int w = 1; w < 8; w++) t += red[w][tx];
                g_cpart[blockIdx.y * DD + x] = t;
            }
        }
    } else {
        __half* dst = (__half*)g_woh;
        const int x = blockIdx.x * 32 + tx;
        const int y0 = blockIdx.y * 32;
        #pragma unroll
        for (int i = ty; i < 32; i += 8) {
            size_t o = (size_t)(y0 + i) * DD + x;
            dst[o] = __float2half(wo[o]);
        }
    }
}

// ---------------- cvec reduction ----------------
__global__ void reduce_cvec_kernel()
{
    int d = blockIdx.x * 256 + threadIdx.x;
    float s = 0.f;
    #pragma unroll
    for (int j = 0; j < 32; j++) s += g_cpart[j * DD + d];
    g_cvec[d] = s;
}

// ---------------- gw / obias from fp16 copies ----------------
__global__ void gw_obias_kernel(const __half* __restrict__ kh, const __half* __restrict__ woh,
                                const float* __restrict__ bv, const float* __restrict__ bo)
{
    const int wid = threadIdx.x >> 5, lane = threadIdx.x & 31;
    const int row = blockIdx.x * 8 + wid;
    if (blockIdx.y == 0) {
        const __half2* mr = (const __half2*)(kh + (size_t)row * DD);
        const float2* cv = (const float2*)g_cvec;
        float s = 0.f;
        #pragma unroll
        for (int m = 0; m < 16; m++) {
            int idx = lane + 32 * m;
            float2 f = __half22float2(mr[idx]);
            float2 c = cv[idx];
            s += f.x * c.x + f.y * c.y;
        }
        #pragma unroll
        for (int o = 16; o > 0; o >>= 1) s += __shfl_xor_sync(0xffffffffu, s, o);
        if (lane == 0) g_gw[row] = CLS_SCALE * s;
    } else {
        if (row >= DD) return;
        const __half2* wr = (const __half2*)(woh + (size_t)row * DD);
        const float2* bv2 = (const float2*)bv;
        float s = 0.f;
        #pragma unroll
        for (int m = 0; m < 16; m++) {
            int idx = lane + 32 * m;
            float2 f = __half22float2(wr[idx]);
            float2 c = bv2[idx];
            s += f.x * c.x + f.y * c.y;
        }
        #pragma unroll
        for (int o = 16; o > 0; o >>= 1) s += __shfl_xor_sync(0xffffffffu, s, o);
        if (lane == 0) g_obias[row] = s + bo[row];
    }
}

// ---------------- fp16 transpose (per batch) ----------------
__global__ void transpose_h_kernel(const __half* __restrict__ V, __half* __restrict__ T)
{
    __shared__ __half tile[32][33];
    const int b = blockIdx.z;
    const __half* Vb = V + (size_t)b * SS * DD;
    __half* Tb = T + (size_t)b * DD * SS;
    const int x = blockIdx.x * 32 + threadIdx.x;
    const int y0 = blockIdx.y * 32;
    #pragma unroll
    for (int i = threadIdx.y; i < 32; i += 8)
        tile[i][threadIdx.x] = Vb[(size_t)(y0 + i) * DD + x];
    __syncthreads();
    const int t = y0 + threadIdx.x;
    #pragma unroll
    for (int i = threadIdx.y; i < 32; i += 8)
        Tb[(size_t)(blockIdx.x * 32 + i) * SS + t] = tile[threadIdx.x][i];
}

// ---------------- launcher (split big pair; interleave SC with VO) ----------------
#define SYMF(ptr, sym) cudaGetSymbolAddress((void**)&ptr, sym)

static cudaStream_t g_s1 = nullptr, g_s2 = nullptr;
static cudaEvent_t  g_evRoot, g_evQKV, g_evW, g_evGW, g_evSM, g_evTR, g_evRS, g_evAW;
static bool g_inited = false;

extern "C" void kernel_launch(void* const* d_in, const int* in_sizes, int n_in,
                              void* d_out, int out_size)
{
    const float* query = (const float*)d_in[0];
    const float* key   = (const float*)d_in[1];
    const float* value = (const float*)d_in[2];
    const float* Wq    = (const float*)d_in[3];
    const float* bq    = (const float*)d_in[4];
    const float* Wk    = (const float*)d_in[5];
    const float* bk    = (const float*)d_in[6];
    const float* Wv    = (const float*)d_in[7];
    const float* bv    = (const float*)d_in[8];
    const float* Wo    = (const float*)d_in[9];
    const float* bo    = (const float*)d_in[10];
    float* out = (float*)d_out;
    (void)bk;

    __half *qh,*kh,*vh,*wTbase,*woh,*W1T,*Gm,*Th,*VO,*VOT,*Ph;
    float *SCp,*obias,*rsum,*Sa,*Ta,*Sb,*Tb,*gw;
    SYMF(qh,g_qh); SYMF(kh,g_kh); SYMF(vh,g_vh);
    SYMF(wTbase,g_wT); SYMF(woh,g_woh);
    SYMF(W1T,g_W1T); SYMF(Gm,g_G);
    SYMF(Th,g_Th); SYMF(VO,g_VO); SYMF(VOT,g_VOT); SYMF(Ph,g_Ph);
    SYMF(SCp,g_SC); SYMF(obias,g_obias); SYMF(rsum,g_rsum);
    SYMF(Sa,g_Sa); SYMF(Ta,g_Ta); SYMF(Sb,g_Sb); SYMF(Tb,g_Tb); SYMF(gw,g_gw);
    __half* WqT = wTbase;
    __half* WkT = wTbase + (size_t)NW;
    __half* WvT = wTbase + (size_t)2*NW;

    const long OUT_N = (long)NM;
    float* attn_out = ((long)out_size >= 2 * OUT_N) ? (out + OUT_N) : nullptr;

    if (!g_inited) {
        cudaStreamCreateWithFlags(&g_s1, cudaStreamNonBlocking);
        cudaStreamCreateWithFlags(&g_s2, cudaStreamNonBlocking);
        cudaEventCreateWithFlags(&g_evRoot, cudaEventDisableTiming);
        cudaEventCreateWithFlags(&g_evQKV,  cudaEventDisableTiming);
        cudaEventCreateWithFlags(&g_evW,    cudaEventDisableTiming);
        cudaEventCreateWithFlags(&g_evGW,   cudaEventDisableTiming);
        cudaEventCreateWithFlags(&g_evSM,   cudaEventDisableTiming);
        cudaEventCreateWithFlags(&g_evTR,   cudaEventDisableTiming);
        cudaEventCreateWithFlags(&g_evRS,   cudaEventDisableTiming);
        cudaEventCreateWithFlags(&g_evAW,   cudaEventDisableTiming);
        cudaFuncSetAttribute(tc_gemm_dual, cudaFuncAttributeMaxDynamicSharedMemorySize, SMEM_GEMM);
        cudaFuncSetAttribute(tc_gemm_one,  cudaFuncAttributeMaxDynamicSharedMemorySize, SMEM_GEMM);
        cudaFuncSetAttribute(tc_gemm_sc,   cudaFuncAttributeMaxDynamicSharedMemorySize, SMEM_GEMM);
        cudaFuncSetAttribute(tc_gemm_fin,  cudaFuncAttributeMaxDynamicSharedMemorySize, SMEM_GEMM);
        g_inited = true;
    }
    cudaStream_t s0 = 0, s1 = g_s1, s2 = g_s2;

    // fork side streams
    cudaEventRecord(g_evRoot, s0);
    cudaStreamWaitEvent(s1, g_evRoot, 0);
    cudaStreamWaitEvent(s2, g_evRoot, 0);

    // s1: input path
    conv_qkv_kernel<<<dim3(NM/2048, 3), 256, 0, s1>>>(query, key, value, qh, kh, vh);
    cudaEventRecord(g_evQKV, s1);

    // s0: weight path (critical)
    conv_w4_kernel<<<dim3(32, 32, 4), dim3(32, 8), 0, s0>>>(Wq, Wk, Wv, Wo, bq);
    cudaEventRecord(g_evW, s0);
    tc_gemm_dual<<<dim3(8, 8, 2), NT_THREADS, SMEM_GEMM, s0>>>(WkT, WqT, W1T, woh, WvT, Gm, DD, DD);
    cudaEventRecord(g_evSM, s0);

    // s2: tables, cvec reduction, gw/obias
    build_tables_kernel<<<TBL_N/256, 256, 0, s2>>>();
    cudaStreamWaitEvent(s2, g_evW, 0);
    reduce_cvec_kernel<<<4, 256, 0, s2>>>();
    cudaStreamWaitEvent(s2, g_evQKV, 0);
    gw_obias_kernel<<<dim3(512, 2), 256, 0, s2>>>(kh, woh, bv, bo);
    cudaEventRecord(g_evGW, s2);

    // s0: Th = q @ W1T^T  (needs qh)
    cudaStreamWaitEvent(s0, g_evQKV, 0);
    tc_gemm_one<<<dim3(8, 32), NT_THREADS, SMEM_GEMM, s0>>>(qh, W1T, Th, DD, DD);

    // s1: VO = v @ G^T  (needs vh [own stream] + small dual) — runs concurrent with Th & SC
    cudaStreamWaitEvent(s1, g_evSM, 0);
    tc_gemm_one<<<dim3(8, 32), NT_THREADS, SMEM_GEMM, s1>>>(vh, Gm, VO, DD, DD);
    transpose_h_kernel<<<dim3(32, 32, BB), dim3(32, 8), 0, s1>>>(VO, VOT);
    cudaEventRecord(g_evTR, s1);

    // s0: SC GEMM (fused quantum+exp) right after Th — overlaps VO on s1
    cudaStreamWaitEvent(s0, g_evGW, 0);
    tc_gemm_sc<<<dim3(8, 8, BB), NT_THREADS, SMEM_GEMM, s0>>>(Th, kh, Ph, SCp, Sa, Ta, Sb, Tb, gw);

    // s0: row sums
    rowsum_kernel<<<BSROWS/8, 256, 0, s0>>>();
    cudaEventRecord(g_evRS, s0);

    // s2: attn output (off critical path)
    if (attn_out) {
        cudaStreamWaitEvent(s2, g_evRS, 0);
        attn_write_kernel<<<BSROWS, 256, 0, s2>>>(attn_out);
        cudaEventRecord(g_evAW, s2);
    }

    // s0: final GEMM (row-scaled, + obias; needs VOT)
    cudaStreamWaitEvent(s0, g_evTR, 0);
    tc_gemm_fin<<<dim3(8, 8, BB), NT_THREADS, SMEM_GEMM, s0>>>(Ph, VOT, out, obias, rsum);

    if (attn_out) cudaStreamWaitEvent(s0, g_evAW, 0);
}

// round 15
// speedup vs baseline: 1.0006x; 1.0006x over previous
#include <cuda_runtime.h>
#include <cuda_fp16.h>
#include <math.h>
#include <stdint.h>

// ---------------- problem constants ----------------
#define BB 4
#define SS 1024
#define DD 1024
#define NQ 8
#define BSROWS (BB*SS)           // 4096
#define CLS_SCALE (0.7f/128.0f)  // ALPHA / (H*sqrt(HEAD_DIM))

#define NM (BSROWS*DD)           // 4,194,304
#define NW (DD*DD)               // 1,048,576

// ---------------- scratch (device globals) ----------------
__device__ uint4 g_qh[NM/8], g_kh[NM/8], g_vh[NM/8];
__device__ uint4 g_wT[3][NW/8];              // WqT, WkT, WvT (fp16, transposed)
__device__ uint4 g_woh[NW/8];                // Wo fp16 (row-major)
__device__ uint4 g_W1T[NW/8], g_G[NW/8];     // composed weights fp16
__device__ uint4 g_Th[NM/8], g_VOT[NM/8], g_Ph[NM/8];
__device__ float g_SC[NM];                   // unnormalized p (fp32)
__device__ float g_Sa[BSROWS], g_Ta[BSROWS], g_Sb[BSROWS], g_Tb[BSROWS];
__device__ float g_cpart[32*DD];
__device__ float g_cvec[DD];
__device__ float g_gw[BSROWS];
__device__ float g_obias[DD];
__device__ float g_rsum[BSROWS];             // 1 / row sum of p

// ---------------- lookup tables ----------------
#define TBL_N   4096
#define TBL_Z0  5.5f
#define TBL_Z1  44.0f
#define TBL_E0f (-16.0f)
#define TBL_E1f (16.0f)
__device__ float4 g_tblZ[TBL_N];   // (ln, dln, rcp, drcp)
__device__ float2 g_tblE[TBL_N];   // (exp, dexp)

__global__ void build_tables_kernel()
{
    int k = blockIdx.x * blockDim.x + threadIdx.x;
    if (k >= TBL_N) return;
    const float hz = (TBL_Z1 - TBL_Z0) / TBL_N;
    float z0 = TBL_Z0 + k * hz, z1 = z0 + hz;
    float l0 = logf(z0), l1 = logf(z1);
    float r0 = 1.0f / z0,  r1 = 1.0f / z1;
    g_tblZ[k] = make_float4(l0, (l1 - l0) / hz, r0, (r1 - r0) / hz);
    const float he = (TBL_E1f - TBL_E0f) / TBL_N;
    float x0 = TBL_E0f + k * he, x1 = x0 + he;
    float e0 = expf(x0), e1 = expf(x1);
    g_tblE[k] = make_float2(e0, (e1 - e0) / he);
}

// ---------------- PTX helpers ----------------
__device__ __forceinline__ uint32_t smem_u32(const void* p) {
    uint32_t a;
    asm("{ .reg .u64 t; cvta.to.shared.u64 t, %1; cvt.u32.u64 %0, t; }" : "=r"(a) : "l"(p));
    return a;
}
__device__ __forceinline__ void cp16(uint32_t dst, const void* src) {
    asm volatile("cp.async.cg.shared.global [%0], [%1], 16;" :: "r"(dst), "l"(src) : "memory");
}
__device__ __forceinline__ void cp_commit() { asm volatile("cp.async.commit_group;" ::: "memory"); }
template<int N>
__device__ __forceinline__ void cp_wait() { asm volatile("cp.async.wait_group %0;" :: "n"(N) : "memory"); }

__device__ __forceinline__ void ldsm4(uint32_t& r0, uint32_t& r1, uint32_t& r2, uint32_t& r3,
                                      uint32_t addr) {
    asm volatile("ldmatrix.sync.aligned.m8n8.x4.shared.b16 {%0,%1,%2,%3}, [%4];"
                 : "=r"(r0), "=r"(r1), "=r"(r2), "=r"(r3) : "r"(addr));
}
__device__ __forceinline__ void mma16816(float* c, const uint32_t* a, const uint32_t* b) {
    asm volatile("mma.sync.aligned.m16n8k16.row.col.f32.f16.f16.f32 "
                 "{%0,%1,%2,%3}, {%4,%5,%6,%7}, {%8,%9}, {%0,%1,%2,%3};"
                 : "+f"(c[0]), "+f"(c[1]), "+f"(c[2]), "+f"(c[3])
                 : "r"(a[0]), "r"(a[1]), "r"(a[2]), "r"(a[3]), "r"(b[0]), "r"(b[1]));
}

// quantum + exp (table-driven)
__device__ __forceinline__ float quantum_exp(float x, float Sa_, float Ta_,
                                             float Sb_, float Tb_, float gw_)
{
    const float HZ = (TBL_Z1 - TBL_Z0) / TBL_N;
    const float INV_HZ = (float)TBL_N / (TBL_Z1 - TBL_Z0);
    const float HE = (TBL_E1f - TBL_E0f) / TBL_N;
    const float INV_HE = (float)TBL_N / (TBL_E1f - TBL_E0f);
    float Z = Sa_ + Sb_;
    float tz = (Z - TBL_Z0) * INV_HZ;
    int kk = (int)tz;
    float4 c4 = __ldg(&g_tblZ[kk]);
    float fz = (Z - TBL_Z0) - HZ * (float)kk;
    float lnZ = fmaf(c4.y, fz, c4.x);
    float rz  = fmaf(c4.w, fz, c4.z);
    float c = x + gw_ + 0.3f * (lnZ - (Ta_ + Tb_) * rz);
    float tx = (c - TBL_E0f) * INV_HE;
    tx = fminf(fmaxf(tx, 0.f), (float)(TBL_N - 1));
    int ke = (int)tx;
    float2 e2 = __ldg(&g_tblE[ke]);
    float fe = (c - TBL_E0f) - HE * (float)ke;
    return fmaf(e2.y, fe, e2.x);
}

// ---------------- fp16 HMMA GEMM core (templated epilogue) ----------------
#define BM 128
#define BN 128
#define BKK 64
#define NT_THREADS 256
#define OFF_B 16384
#define STAGE_BYTES 32768
#define NSTAGE 3
#define SMEM_GEMM (NSTAGE*STAGE_BYTES)

__device__ __forceinline__ void load_stage(
    uint32_t st, const __half* a, const __half* b, int K, int k0, int tid)
{
    #pragma unroll
    for (int i = 0; i < 4; i++) {
        int id = tid + i * 256;
        int r = id >> 3, c = id & 7;
        uint32_t off = (uint32_t)(r * 128 + ((c ^ (r & 7)) << 4));
        size_t ge = (size_t)r * K + k0 + c * 8;
        cp16(st + off,         a + ge);
        cp16(st + OFF_B + off, b + ge);
    }
}

template<int EPI>
__device__ __forceinline__ void gemm_core(
    const __half* __restrict__ a_p, const __half* __restrict__ b_p,
    float* __restrict__ Cf, __half* __restrict__ Ch,
    const float* __restrict__ bias, float scale, int K, int ldc,
    int row_base, int col_base, char* smem,
    const float* qSa, const float* qTa, const float* qSb, const float* qTb,
    const float* qgw, float* Pf, const float* rs)
{
    const uint32_t sbase = smem_u32(smem);
    const int tid  = threadIdx.x;
    const int lane = tid & 31;
    const int wid  = tid >> 5;
    const int warp_m = wid >> 2;
    const int warp_n = wid & 3;
    const int g = lane >> 3;
    const int r = lane & 7;

    float acc[4][4][4];
    #pragma unroll
    for (int i = 0; i < 4; i++)
        #pragma unroll
        for (int j = 0; j < 4; j++)
            #pragma unroll
            for (int q = 0; q < 4; q++) acc[i][j][q] = 0.f;

    const int NKB = K / BKK;

    load_stage(sbase, a_p, b_p, K, 0, tid);
    cp_commit();
    load_stage(sbase + STAGE_BYTES, a_p, b_p, K, BKK, tid);
    cp_commit();

    int sidx = 0;
    for (int kb = 0; kb < NKB; kb++) {
        if (kb + 1 < NKB) cp_wait<1>(); else cp_wait<0>();
        __syncthreads();

        if (kb + 2 < NKB) {
            int s2 = sidx + 2; if (s2 >= NSTAGE) s2 -= NSTAGE;
            load_stage(sbase + s2 * STAGE_BYTES, a_p, b_p, K, (kb + 2) * BKK, tid);
            cp_commit();
        }

        const uint32_t st = sbase + sidx * STAGE_BYTES;
        #pragma unroll
        for (int ks = 0; ks < 4; ks++) {
            uint32_t ah[4][4], bh[4][2];
            const int cA = ((2 * ks + (g >> 1)) ^ r) << 4;
            #pragma unroll
            for (int mi = 0; mi < 4; mi++) {
                uint32_t rowA = warp_m * 64 + mi * 16 + ((g & 1) << 3) + r;
                ldsm4(ah[mi][0], ah[mi][1], ah[mi][2], ah[mi][3], st + rowA * 128 + cA);
            }
            const int cB = ((2 * ks + (g & 1)) ^ r) << 4;
            #pragma unroll
            for (int p = 0; p < 2; p++) {
                uint32_t rowB = warp_n * 32 + ((2 * p + (g >> 1)) << 3) + r;
                uint32_t t0, t1, t2, t3;
                ldsm4(t0, t1, t2, t3, st + OFF_B + rowB * 128 + cB);
                bh[2*p][0] = t0; bh[2*p][1] = t1; bh[2*p+1][0] = t2; bh[2*p+1][1] = t3;
            }
            #pragma unroll
            for (int mi = 0; mi < 4; mi++)
                #pragma unroll
                for (int ni = 0; ni < 4; ni++)
                    mma16816(acc[mi][ni], ah[mi], bh[ni]);
        }
        sidx++; if (sidx >= NSTAGE) sidx = 0;
    }

    #pragma unroll
    for (int mi = 0; mi < 4; mi++) {
        #pragma unroll
        for (int ni = 0; ni < 4; ni++) {
            const int row0 = row_base + warp_m * 64 + mi * 16 + (lane >> 2);
            const int col  = col_base + warp_n * 32 + ni * 8 + 2 * (lane & 3);
            #pragma unroll
            for (int h = 0; h < 2; h++) {
                float x0 = acc[mi][ni][2*h + 0] * scale;
                float x1 = acc[mi][ni][2*h + 1] * scale;
                const int row = row0 + 8*h;
                const size_t o = (size_t)row * ldc + col;
                if (EPI == 0) {
                    union { __half b[2]; uint32_t u; } H;
                    H.b[0] = __float2half(x0); H.b[1] = __float2half(x1);
                    *(uint32_t*)&Ch[o] = H.u;
                } else if (EPI == 1) {
                    float Sa_ = __ldg(qSa + row), Ta_ = __ldg(qTa + row);
                    float p0 = quantum_exp(x0, Sa_, Ta_, __ldg(qSb + col),
                                           __ldg(qTb + col), __ldg(qgw + col));
                    float p1 = quantum_exp(x1, Sa_, Ta_, __ldg(qSb + col + 1),
                                           __ldg(qTb + col + 1), __ldg(qgw + col + 1));
                    *(float2*)&Pf[o] = make_float2(p0, p1);
                    union { __half b[2]; uint32_t u; } H;
                    H.b[0] = __float2half(p0); H.b[1] = __float2half(p1);
                    *(uint32_t*)&Ch[o] = H.u;
                } else {  // EPI == 2
                    float r_ = __ldg(rs + row);
                    float y0 = fmaf(x0, r_, __ldg(bias + col));
                    float y1 = fmaf(x1, r_, __ldg(bias + col + 1));
                    *(float2*)&Cf[o] = make_float2(y0, y1);
                }
            }
        }
    }
}

// dual NT GEMM (EPI0): z=0/1 selects job (small composed pair OR big q/v pair)
__global__ __launch_bounds__(NT_THREADS, 2)
void tc_gemm_dual(const __half* __restrict__ A0, const __half* __restrict__ B0, __half* __restrict__ C0,
                  const __half* __restrict__ A1, const __half* __restrict__ B1, __half* __restrict__ C1,
                  int K, int ldc)
{
    extern __shared__ char smem[];
    const __half* A = blockIdx.z ? A1 : A0;
    const __half* B = blockIdx.z ? B1 : B0;
    __half*       C = blockIdx.z ? C1 : C0;
    gemm_core<0>(A + (size_t)blockIdx.y * BM * K,
                 B + (size_t)blockIdx.x * BN * K,
                 nullptr, C, nullptr, 1.0f, K, ldc,
                 blockIdx.y * BM, blockIdx.x * BN, smem,
                 nullptr, nullptr, nullptr, nullptr, nullptr, nullptr, nullptr);
}

// batched VOT GEMM (EPI0): VOT[b] = G @ v[b]^T  (A=G shared across batches)
__global__ __launch_bounds__(NT_THREADS, 2)
void tc_gemm_vot(const __half* __restrict__ G, const __half* __restrict__ v,
                 __half* __restrict__ VOT)
{
    extern __shared__ char smem[];
    const long z = blockIdx.z;
    gemm_core<0>(G + (size_t)blockIdx.y * BM * DD,
                 v + z * (long)SS * DD + (size_t)blockIdx.x * BN * DD,
                 nullptr, VOT + z * (long)DD * SS, nullptr, 1.0f, DD, SS,
                 blockIdx.y * BM, blockIdx.x * BN, smem,
                 nullptr, nullptr, nullptr, nullptr, nullptr, nullptr, nullptr);
}

// batched SC GEMM with fused quantum+exp epilogue (EPI1)
__global__ __launch_bounds__(NT_THREADS, 2)
void tc_gemm_sc(const __half* __restrict__ A, const __half* __restrict__ B,
                __half* __restrict__ Ph, float* __restrict__ Pf,
                const float* __restrict__ Sa, const float* __restrict__ Ta,
                const float* __restrict__ Sb, const float* __restrict__ Tb,
                const float* __restrict__ gw)
{
    extern __shared__ char smem[];
    const long z = blockIdx.z;
    gemm_core<1>(A + z * (long)SS * DD + (size_t)blockIdx.y * BM * DD,
                 B + z * (long)SS * DD + (size_t)blockIdx.x * BN * DD,
                 nullptr, Ph + z * (long)SS * SS,
                 nullptr, CLS_SCALE, DD, SS,
                 blockIdx.y * BM, blockIdx.x * BN, smem,
                 Sa + z * SS, Ta + z * SS, Sb + z * SS, Tb + z * SS,
                 gw + z * SS, Pf + z * (long)SS * SS, nullptr);
}

// batched final GEMM with row-scaled output (EPI2)
__global__ __launch_bounds__(NT_THREADS, 2)
void tc_gemm_fin(const __half* __restrict__ A, const __half* __restrict__ B,
                 float* __restrict__ Cf, const float* __restrict__ bias,
                 const float* __restrict__ rs)
{
    extern __shared__ char smem[];
    const long z = blockIdx.z;
    gemm_core<2>(A + z * (long)SS * SS + (size_t)blockIdx.y * BM * SS,
                 B + z * (long)DD * SS + (size_t)blockIdx.x * BN * SS,
                 Cf + z * (long)SS * DD, nullptr,
                 bias, 1.0f, SS, DD,
                 blockIdx.y * BM, blockIdx.x * BN, smem,
                 nullptr, nullptr, nullptr, nullptr, nullptr, nullptr,
                 rs + z * SS);
}

// ---------------- row sums ----------------
__global__ void rowsum_kernel()
{
    const int row  = blockIdx.x * 8 + (threadIdx.x >> 5);
    const int lane = threadIdx.x & 31;
    const float4* pr = (const float4*)(g_SC + (size_t)row * SS);
    float s = 0.f;
    #pragma unroll
    for (int i = 0; i < 8; i++) {
        float4 v = pr[lane + 32 * i];
        s += v.x + v.y + v.z + v.w;
    }
    #pragma unroll
    for (int o = 16; o > 0; o >>= 1) s += __shfl_xor_sync(0xffffffffu, s, o);
    if (lane == 0) g_rsum[row] = 1.0f / s;
}

// ---------------- attn output: attn = p32 * inv ----------------
__global__ __launch_bounds__(256)
void attn_write_kernel(float* __restrict__ attn)
{
    const int row = blockIdx.x;
    const int j0 = threadIdx.x * 4;
    const float inv = g_rsum[row];
    float4 v = *(const float4*)&g_SC[(size_t)row * SS + j0];
    v.x *= inv; v.y *= inv; v.z *= inv; v.w *= inv;
    *(float4*)&attn[(size_t)row * SS + j0] = v;
}

// ---------------- fused q/k/v conversion + row stats ----------------
__global__ __launch_bounds__(256)
void conv_qkv_kernel(const float* __restrict__ q, const float* __restrict__ k,
                     const float* __restrict__ v,
                     __half* __restrict__ qh, __half* __restrict__ kh,
                     __half* __restrict__ vh)
{
    const int which = blockIdx.y;
    const float* src = (which == 0) ? q : (which == 1) ? k : v;
    __half* dst      = (which == 0) ? qh : (which == 1) ? kh : vh;

    int i = (blockIdx.x * blockDim.x + threadIdx.x) * 8;
    float4 v0 = *(const float4*)(src + i);
    float4 v1 = *(const float4*)(src + i + 4);
    float x[8] = {v0.x, v0.y, v0.z, v0.w, v1.x, v1.y, v1.z, v1.w};
    union { uint4 qd; __half b[8]; } H;
    #pragma unroll
    for (int j = 0; j < 8; j++) H.b[j] = __float2half(x[j]);
    *(uint4*)(dst + i) = H.qd;

    if (which < 2 && (i & (DD - 1)) == 0) {
        float s = 0.f, t = 0.f;
        #pragma unroll
        for (int m = 0; m < NQ; m++) {
            float tv = tanhf(x[m]);
            float a = expf(tv);
            s += a; t += a * tv;
        }
        int row = i >> 10;
        if (which == 0) { g_Sa[row] = s; g_Ta[row] = t; }
        else            { g_Sb[row] = s; g_Tb[row] = t; }
    }
}

// ---------------- weight conversion + fused cvec partials ----------------
__global__ void conv_w4_kernel(const float* __restrict__ wq, const float* __restrict__ wk,
                               const float* __restrict__ wv, const float* __restrict__ wo,
                               const float* __restrict__ bq)
{
    const int which = blockIdx.z;
    __shared__ float tile[32][33];
    __shared__ float red[8][32];
    const int tx = threadIdx.x, ty = threadIdx.y;
    if (which < 3) {
        const float* src = (which == 0) ? wq : (which == 1) ? wk : wv;
        __half* dst = (__half*)g_wT[which];
        const int x = blockIdx.x * 32 + tx;
        const int y0 = blockIdx.y * 32;
        #pragma unroll
        for (int i = ty; i < 32; i += 8)
            tile[i][tx] = src[(size_t)(y0 + i) * DD + x];
        __syncthreads();
        #pragma unroll
        for (int i = ty; i < 32; i += 8)
            dst[(size_t)(blockIdx.x * 32 + i) * DD + y0 + tx] = __float2half(tile[tx][i]);
        if (which == 1) {
            float p = 0.f;
            #pragma unroll
            for (int i = 0; i < 4; i++)
                p += bq[y0 + ty * 4 + i] * tile[ty * 4 + i][tx];
            red[ty][tx] = p;
            __syncthreads();
            if (ty == 0) {
                float t = red[0][tx];
                #pragma unroll
                for (int w = 1; w < 8; w++) t += red[w][tx];
                g_cpart[blockIdx.y * DD + x] = t;
            }
        }
    } else {
        __half* dst = (__half*)g_woh;
        const int x = blockIdx.x * 32 + tx;
        const int y0 = blockIdx.y * 32;
        #pragma unroll
        for (int i = ty; i < 32; i += 8) {
            size_t o = (size_t)(y0 + i) * DD + x;
            dst[o] = __float2half(wo[o]);
        }
    }
}

// ---------------- cvec reduction ----------------
__global__ void reduce_cvec_kernel()
{
    int d = blockIdx.x * 256 + threadIdx.x;
    float s = 0.f;
    #pragma unroll
    for (int j = 0; j < 32; j++) s += g_cpart[j * DD + d];
    g_cvec[d] = s;
}

// ---------------- gw / obias from fp16 copies ----------------
__global__ void gw_obias_kernel(const __half* __restrict__ kh, const __half* __restrict__ woh,
                                const float* __restrict__ bv, const float* __restrict__ bo)
{
    const int wid = threadIdx.x >> 5, lane = threadIdx.x & 31;
    const int row = blockIdx.x * 8 + wid;
    if (blockIdx.y == 0) {
        const __half2* mr = (const __half2*)(kh + (size_t)row * DD);
        const float2* cv = (const float2*)g_cvec;
        float s = 0.f;
        #pragma unroll
        for (int m = 0; m < 16; m++) {
            int idx = lane + 32 * m;
            float2 f = __half22float2(mr[idx]);
            float2 c = cv[idx];
            s += f.x * c.x + f.y * c.y;
        }
        #pragma unroll
        for (int o = 16; o > 0; o >>= 1) s += __shfl_xor_sync(0xffffffffu, s, o);
        if (lane == 0) g_gw[row] = CLS_SCALE * s;
    } else {
        if (row >= DD) return;
        const __half2* wr = (const __half2*)(woh + (size_t)row * DD);
        const float2* bv2 = (const float2*)bv;
        float s = 0.f;
        #pragma unroll
        for (int m = 0; m < 16; m++) {
            int idx = lane + 32 * m;
            float2 f = __half22float2(wr[idx]);
            float2 c = bv2[idx];
            s += f.x * c.x + f.y * c.y;
        }
        #pragma unroll
        for (int o = 16; o > 0; o >>= 1) s += __shfl_xor_sync(0xffffffffu, s, o);
        if (lane == 0) g_obias[row] = s + bo[row];
    }
}

// ---------------- launcher (R13 shape; VOT computed directly) ----------------
#define SYMF(ptr, sym) cudaGetSymbolAddress((void**)&ptr, sym)

static cudaStream_t g_s1 = nullptr, g_s2 = nullptr;
static cudaEvent_t  g_evRoot, g_evQKV, g_evW, g_evGW, g_evBIG, g_evTR, g_evRS, g_evAW;
static bool g_inited = false;

extern "C" void kernel_launch(void* const* d_in, const int* in_sizes, int n_in,
                              void* d_out, int out_size)
{
    const float* query = (const float*)d_in[0];
    const float* key   = (const float*)d_in[1];
    const float* value = (const float*)d_in[2];
    const float* Wq    = (const float*)d_in[3];
    const float* bq    = (const float*)d_in[4];
    const float* Wk    = (const float*)d_in[5];
    const float* bk    = (const float*)d_in[6];
    const float* Wv    = (const float*)d_in[7];
    const float* bv    = (const float*)d_in[8];
    const float* Wo    = (const float*)d_in[9];
    const float* bo    = (const float*)d_in[10];
    float* out = (float*)d_out;
    (void)bk;

    __half *qh,*kh,*vh,*wTbase,*woh,*W1T,*Gm,*Th,*VOT,*Ph;
    float *SCp,*obias,*rsum,*Sa,*Ta,*Sb,*Tb,*gw;
    SYMF(qh,g_qh); SYMF(kh,g_kh); SYMF(vh,g_vh);
    SYMF(wTbase,g_wT); SYMF(woh,g_woh);
    SYMF(W1T,g_W1T); SYMF(Gm,g_G);
    SYMF(Th,g_Th); SYMF(VOT,g_VOT); SYMF(Ph,g_Ph);
    SYMF(SCp,g_SC); SYMF(obias,g_obias); SYMF(rsum,g_rsum);
    SYMF(Sa,g_Sa); SYMF(Ta,g_Ta); SYMF(Sb,g_Sb); SYMF(Tb,g_Tb); SYMF(gw,g_gw);
    __half* WqT = wTbase;
    __half* WkT = wTbase + (size_t)NW;
    __half* WvT = wTbase + (size_t)2*NW;

    const long OUT_N = (long)NM;
    float* attn_out = ((long)out_size >= 2 * OUT_N) ? (out + OUT_N) : nullptr;

    if (!g_inited) {
        cudaStreamCreateWithFlags(&g_s1, cudaStreamNonBlocking);
        cudaStreamCreateWithFlags(&g_s2, cudaStreamNonBlocking);
        cudaEventCreateWithFlags(&g_evRoot, cudaEventDisableTiming);
        cudaEventCreateWithFlags(&g_evQKV,  cudaEventDisableTiming);
        cudaEventCreateWithFlags(&g_evW,    cudaEventDisableTiming);
        cudaEventCreateWithFlags(&g_evGW,   cudaEventDisableTiming);
        cudaEventCreateWithFlags(&g_evBIG,  cudaEventDisableTiming);
        cudaEventCreateWithFlags(&g_evTR,   cudaEventDisableTiming);
        cudaEventCreateWithFlags(&g_evRS,   cudaEventDisableTiming);
        cudaEventCreateWithFlags(&g_evAW,   cudaEventDisableTiming);
        cudaFuncSetAttribute(tc_gemm_dual, cudaFuncAttributeMaxDynamicSharedMemorySize, SMEM_GEMM);
        cudaFuncSetAttribute(tc_gemm_vot,  cudaFuncAttributeMaxDynamicSharedMemorySize, SMEM_GEMM);
        cudaFuncSetAttribute(tc_gemm_sc,   cudaFuncAttributeMaxDynamicSharedMemorySize, SMEM_GEMM);
        cudaFuncSetAttribute(tc_gemm_fin,  cudaFuncAttributeMaxDynamicSharedMemorySize, SMEM_GEMM);
        g_inited = true;
    }
    cudaStream_t s0 = 0, s1 = g_s1, s2 = g_s2;

    // fork side streams
    cudaEventRecord(g_evRoot, s0);
    cudaStreamWaitEvent(s1, g_evRoot, 0);
    cudaStreamWaitEvent(s2, g_evRoot, 0);

    // s1: input path
    conv_qkv_kernel<<<dim3(NM/2048, 3), 256, 0, s1>>>(query, key, value, qh, kh, vh);
    cudaEventRecord(g_evQKV, s1);

    // s0: weight path (critical)
    conv_w4_kernel<<<dim3(32, 32, 4), dim3(32, 8), 0, s0>>>(Wq, Wk, Wv, Wo, bq);
    cudaEventRecord(g_evW, s0);
    tc_gemm_dual<<<dim3(8, 8, 2), NT_THREADS, SMEM_GEMM, s0>>>(WkT, WqT, W1T, woh, WvT, Gm, DD, DD);

    // s2: tables, cvec reduction, gw/obias
    build_tables_kernel<<<TBL_N/256, 256, 0, s2>>>();
    cudaStreamWaitEvent(s2, g_evW, 0);
    reduce_cvec_kernel<<<4, 256, 0, s2>>>();
    cudaStreamWaitEvent(s2, g_evQKV, 0);
    gw_obias_kernel<<<dim3(512, 2), 256, 0, s2>>>(kh, woh, bv, bo);
    cudaEventRecord(g_evGW, s2);

    // s0: Th = q @ W1T^T  (big, 256 CTAs)
    cudaStreamWaitEvent(s0, g_evQKV, 0);
    tc_gemm_dual<<<dim3(8, 32, 1), NT_THREADS, SMEM_GEMM, s0>>>(qh, W1T, Th, nullptr, nullptr, nullptr, DD, DD);

    // s0: VOT[b] = G @ v[b]^T directly (replaces VO GEMM + transpose)
    tc_gemm_vot<<<dim3(8, 8, BB), NT_THREADS, SMEM_GEMM, s0>>>(Gm, vh, VOT);
    cudaEventRecord(g_evTR, s0);

    // s0: SC GEMM (fused quantum+exp; needs gw/tables)
    cudaStreamWaitEvent(s0, g_evGW, 0);
    tc_gemm_sc<<<dim3(8, 8, BB), NT_THREADS, SMEM_GEMM, s0>>>(Th, kh, Ph, SCp, Sa, Ta, Sb, Tb, gw);

    // s0: row sums
    rowsum_kernel<<<BSROWS/8, 256, 0, s0>>>();
    cudaEventRecord(g_evRS, s0);

    // s1: attn output (off critical path)
    if (attn_out) {
        cudaStreamWaitEvent(s1, g_evRS, 0);
        attn_write_kernel<<<BSROWS, 256, 0, s1>>>(attn_out);
        cudaEventRecord(g_evAW, s1);
    }

    // s0: final GEMM (row-scaled, + obias; VOT from same stream order)
    tc_gemm_fin<<<dim3(8, 8, BB), NT_THREADS, SMEM_GEMM, s0>>>(Ph, VOT, out, obias, rsum);

    if (attn_out) cudaStreamWaitEvent(s0, g_evAW, 0);
}

// round 16
// speedup vs baseline: 1.0252x; 1.0246x over previous
#include <cuda_runtime.h>
#include <cuda_fp16.h>
#include <math.h>
#include <stdint.h>

// ---------------- problem constants ----------------
#define BB 4
#define SS 1024
#define DD 1024
#define NQ 8
#define BSROWS (BB*SS)           // 4096
#define CLS_SCALE (0.7f/128.0f)  // ALPHA / (H*sqrt(HEAD_DIM))

#define NM (BSROWS*DD)           // 4,194,304
#define NW (DD*DD)               // 1,048,576

// ---------------- scratch (device globals) ----------------
__device__ uint4 g_qh[NM/8], g_kh[NM/8], g_vh[NM/8];
__device__ uint4 g_wT[3][NW/8];              // WqT, WkT, WvT (fp16, transposed)
__device__ uint4 g_woh[NW/8];                // Wo fp16 (row-major)
__device__ uint4 g_W1T[NW/8], g_G[NW/8];     // composed weights fp16
__device__ uint4 g_Th[NM/8], g_VOT[NM/8], g_Ph[NM/8];
__device__ float g_SC[NM];                   // unnormalized p (fp32)
__device__ float g_Sa[BSROWS], g_Ta[BSROWS], g_Sb[BSROWS], g_Tb[BSROWS];
__device__ float g_cpart[32*DD];
__device__ float g_cvec[DD];
__device__ float g_gw[BSROWS];
__device__ float g_obias[DD];
__device__ float g_rsum[BSROWS];             // 1 / row sum of p

// ---------------- lookup tables ----------------
#define TBL_N   4096
#define TBL_Z0  5.5f
#define TBL_Z1  44.0f
#define TBL_E0f (-16.0f)
#define TBL_E1f (16.0f)
__device__ float4 g_tblZ[TBL_N];   // (ln, dln, rcp, drcp)
__device__ float2 g_tblE[TBL_N];   // (exp, dexp)

__global__ void build_tables_kernel()
{
    int k = blockIdx.x * blockDim.x + threadIdx.x;
    if (k >= TBL_N) return;
    const float hz = (TBL_Z1 - TBL_Z0) / TBL_N;
    float z0 = TBL_Z0 + k * hz, z1 = z0 + hz;
    float l0 = logf(z0), l1 = logf(z1);
    float r0 = 1.0f / z0,  r1 = 1.0f / z1;
    g_tblZ[k] = make_float4(l0, (l1 - l0) / hz, r0, (r1 - r0) / hz);
    const float he = (TBL_E1f - TBL_E0f) / TBL_N;
    float x0 = TBL_E0f + k * he, x1 = x0 + he;
    float e0 = expf(x0), e1 = expf(x1);
    g_tblE[k] = make_float2(e0, (e1 - e0) / he);
}

// ---------------- PTX helpers ----------------
__device__ __forceinline__ uint32_t smem_u32(const void* p) {
    uint32_t a;
    asm("{ .reg .u64 t; cvta.to.shared.u64 t, %1; cvt.u32.u64 %0, t; }" : "=r"(a) : "l"(p));
    return a;
}
__device__ __forceinline__ void cp16(uint32_t dst, const void* src) {
    asm volatile("cp.async.cg.shared.global [%0], [%1], 16;" :: "r"(dst), "l"(src) : "memory");
}
__device__ __forceinline__ void cp_commit() { asm volatile("cp.async.commit_group;" ::: "memory"); }
template<int N>
__device__ __forceinline__ void cp_wait() { asm volatile("cp.async.wait_group %0;" :: "n"(N) : "memory"); }

__device__ __forceinline__ void ldsm4(uint32_t& r0, uint32_t& r1, uint32_t& r2, uint32_t& r3,
                                      uint32_t addr) {
    asm volatile("ldmatrix.sync.aligned.m8n8.x4.shared.b16 {%0,%1,%2,%3}, [%4];"
                 : "=r"(r0), "=r"(r1), "=r"(r2), "=r"(r3) : "r"(addr));
}
__device__ __forceinline__ void mma16816(float* c, const uint32_t* a, const uint32_t* b) {
    asm volatile("mma.sync.aligned.m16n8k16.row.col.f32.f16.f16.f32 "
                 "{%0,%1,%2,%3}, {%4,%5,%6,%7}, {%8,%9}, {%0,%1,%2,%3};"
                 : "+f"(c[0]), "+f"(c[1]), "+f"(c[2]), "+f"(c[3])
                 : "r"(a[0]), "r"(a[1]), "r"(a[2]), "r"(a[3]), "r"(b[0]), "r"(b[1]));
}

// quantum + exp (table-driven)
__device__ __forceinline__ float quantum_exp(float x, float Sa_, float Ta_,
                                             float Sb_, float Tb_, float gw_)
{
    const float HZ = (TBL_Z1 - TBL_Z0) / TBL_N;
    const float INV_HZ = (float)TBL_N / (TBL_Z1 - TBL_Z0);
    const float HE = (TBL_E1f - TBL_E0f) / TBL_N;
    const float INV_HE = (float)TBL_N / (TBL_E1f - TBL_E0f);
    float Z = Sa_ + Sb_;
    float tz = (Z - TBL_Z0) * INV_HZ;
    int kk = (int)tz;
    float4 c4 = __ldg(&g_tblZ[kk]);
    float fz = (Z - TBL_Z0) - HZ * (float)kk;
    float lnZ = fmaf(c4.y, fz, c4.x);
    float rz  = fmaf(c4.w, fz, c4.z);
    float c = x + gw_ + 0.3f * (lnZ - (Ta_ + Tb_) * rz);
    float tx = (c - TBL_E0f) * INV_HE;
    tx = fminf(fmaxf(tx, 0.f), (float)(TBL_N - 1));
    int ke = (int)tx;
    float2 e2 = __ldg(&g_tblE[ke]);
    float fe = (c - TBL_E0f) - HE * (float)ke;
    return fmaf(e2.y, fe, e2.x);
}

// ---------------- fp16 HMMA GEMM core (templated epilogue) ----------------
#define BM 128
#define BN 128
#define BKK 64
#define NT_THREADS 256
#define OFF_B 16384
#define STAGE_BYTES 32768
#define NSTAGE 3
#define SMEM_GEMM (NSTAGE*STAGE_BYTES)

__device__ __forceinline__ void load_stage(
    uint32_t st, const __half* a, const __half* b, int K, int k0, int tid)
{
    #pragma unroll
    for (int i = 0; i < 4; i++) {
        int id = tid + i * 256;
        int r = id >> 3, c = id & 7;
        uint32_t off = (uint32_t)(r * 128 + ((c ^ (r & 7)) << 4));
        size_t ge = (size_t)r * K + k0 + c * 8;
        cp16(st + off,         a + ge);
        cp16(st + OFF_B + off, b + ge);
    }
}

template<int EPI>
__device__ __forceinline__ void gemm_core(
    const __half* __restrict__ a_p, const __half* __restrict__ b_p,
    float* __restrict__ Cf, __half* __restrict__ Ch,
    const float* __restrict__ bias, float scale, int K, int ldc,
    int row_base, int col_base, char* smem,
    const float* qSa, const float* qTa, const float* qSb, const float* qTb,
    const float* qgw, float* Pf, const float* rs)
{
    const uint32_t sbase = smem_u32(smem);
    const int tid  = threadIdx.x;
    const int lane = tid & 31;
    const int wid  = tid >> 5;
    const int warp_m = wid >> 2;
    const int warp_n = wid & 3;
    const int g = lane >> 3;
    const int r = lane & 7;

    float acc[4][4][4];
    #pragma unroll
    for (int i = 0; i < 4; i++)
        #pragma unroll
        for (int j = 0; j < 4; j++)
            #pragma unroll
            for (int q = 0; q < 4; q++) acc[i][j][q] = 0.f;

    const int NKB = K / BKK;

    load_stage(sbase, a_p, b_p, K, 0, tid);
    cp_commit();
    load_stage(sbase + STAGE_BYTES, a_p, b_p, K, BKK, tid);
    cp_commit();

    int sidx = 0;
    for (int kb = 0; kb < NKB; kb++) {
        if (kb + 1 < NKB) cp_wait<1>(); else cp_wait<0>();
        __syncthreads();

        if (kb + 2 < NKB) {
            int s2 = sidx + 2; if (s2 >= NSTAGE) s2 -= NSTAGE;
            load_stage(sbase + s2 * STAGE_BYTES, a_p, b_p, K, (kb + 2) * BKK, tid);
            cp_commit();
        }

        const uint32_t st = sbase + sidx * STAGE_BYTES;
        #pragma unroll
        for (int ks = 0; ks < 4; ks++) {
            uint32_t ah[4][4], bh[4][2];
            const int cA = ((2 * ks + (g >> 1)) ^ r) << 4;
            #pragma unroll
            for (int mi = 0; mi < 4; mi++) {
                uint32_t rowA = warp_m * 64 + mi * 16 + ((g & 1) << 3) + r;
                ldsm4(ah[mi][0], ah[mi][1], ah[mi][2], ah[mi][3], st + rowA * 128 + cA);
            }
            const int cB = ((2 * ks + (g & 1)) ^ r) << 4;
            #pragma unroll
            for (int p = 0; p < 2; p++) {
                uint32_t rowB = warp_n * 32 + ((2 * p + (g >> 1)) << 3) + r;
                uint32_t t0, t1, t2, t3;
                ldsm4(t0, t1, t2, t3, st + OFF_B + rowB * 128 + cB);
                bh[2*p][0] = t0; bh[2*p][1] = t1; bh[2*p+1][0] = t2; bh[2*p+1][1] = t3;
            }
            #pragma unroll
            for (int mi = 0; mi < 4; mi++)
                #pragma unroll
                for (int ni = 0; ni < 4; ni++)
                    mma16816(acc[mi][ni], ah[mi], bh[ni]);
        }
        sidx++; if (sidx >= NSTAGE) sidx = 0;
    }

    #pragma unroll
    for (int mi = 0; mi < 4; mi++) {
        #pragma unroll
        for (int ni = 0; ni < 4; ni++) {
            const int row0 = row_base + warp_m * 64 + mi * 16 + (lane >> 2);
            const int col  = col_base + warp_n * 32 + ni * 8 + 2 * (lane & 3);
            #pragma unroll
            for (int h = 0; h < 2; h++) {
                float x0 = acc[mi][ni][2*h + 0] * scale;
                float x1 = acc[mi][ni][2*h + 1] * scale;
                const int row = row0 + 8*h;
                const size_t o = (size_t)row * ldc + col;
                if (EPI == 0) {
                    union { __half b[2]; uint32_t u; } H;
                    H.b[0] = __float2half(x0); H.b[1] = __float2half(x1);
                    *(uint32_t*)&Ch[o] = H.u;
                } else if (EPI == 1) {
                    float Sa_ = __ldg(qSa + row), Ta_ = __ldg(qTa + row);
                    float p0 = quantum_exp(x0, Sa_, Ta_, __ldg(qSb + col),
                                           __ldg(qTb + col), __ldg(qgw + col));
                    float p1 = quantum_exp(x1, Sa_, Ta_, __ldg(qSb + col + 1),
                                           __ldg(qTb + col + 1), __ldg(qgw + col + 1));
                    *(float2*)&Pf[o] = make_float2(p0, p1);
                    union { __half b[2]; uint32_t u; } H;
                    H.b[0] = __float2half(p0); H.b[1] = __float2half(p1);
                    *(uint32_t*)&Ch[o] = H.u;
                } else {  // EPI == 2
                    float r_ = __ldg(rs + row);
                    float y0 = fmaf(x0, r_, __ldg(bias + col));
                    float y1 = fmaf(x1, r_, __ldg(bias + col + 1));
                    *(float2*)&Cf[o] = make_float2(y0, y1);
                }
            }
        }
    }
}

// dual NT GEMM (EPI0): small composed-weight pair
__global__ __launch_bounds__(NT_THREADS, 2)
void tc_gemm_dual(const __half* __restrict__ A0, const __half* __restrict__ B0, __half* __restrict__ C0,
                  const __half* __restrict__ A1, const __half* __restrict__ B1, __half* __restrict__ C1,
                  int K, int ldc)
{
    extern __shared__ char smem[];
    const __half* A = blockIdx.z ? A1 : A0;
    const __half* B = blockIdx.z ? B1 : B0;
    __half*       C = blockIdx.z ? C1 : C0;
    gemm_core<0>(A + (size_t)blockIdx.y * BM * K,
                 B + (size_t)blockIdx.x * BN * K,
                 nullptr, C, nullptr, 1.0f, K, ldc,
                 blockIdx.y * BM, blockIdx.x * BN, smem,
                 nullptr, nullptr, nullptr, nullptr, nullptr, nullptr, nullptr);
}

// combined big GEMM (EPI0), grid (8,32,2):
//   z=0: Th = q @ W1T^T        (by = M tile 0..31, ldc=DD)
//   z=1: VOT[b] = G @ v[b]^T   (by = b*8 + M tile, ldc=SS)
__global__ __launch_bounds__(NT_THREADS, 2)
void tc_gemm_big(const __half* __restrict__ qh, const __half* __restrict__ W1T,
                 __half* __restrict__ Th,
                 const __half* __restrict__ G, const __half* __restrict__ v,
                 __half* __restrict__ VOT)
{
    extern __shared__ char smem[];
    if (blockIdx.z == 0) {
        gemm_core<0>(qh + (size_t)blockIdx.y * BM * DD,
                     W1T + (size_t)blockIdx.x * BN * DD,
                     nullptr, Th, nullptr, 1.0f, DD, DD,
                     blockIdx.y * BM, blockIdx.x * BN, smem,
                     nullptr, nullptr, nullptr, nullptr, nullptr, nullptr, nullptr);
    } else {
        const int b = blockIdx.y >> 3;        // batch
        const int yt = blockIdx.y & 7;        // M tile within G
        gemm_core<0>(G + (size_t)yt * BM * DD,
                     v + (size_t)b * SS * DD + (size_t)blockIdx.x * BN * DD,
                     nullptr, VOT + (size_t)b * DD * SS, nullptr, 1.0f, DD, SS,
                     yt * BM, blockIdx.x * BN, smem,
                     nullptr, nullptr, nullptr, nullptr, nullptr, nullptr, nullptr);
    }
}

// batched SC GEMM with fused quantum+exp epilogue (EPI1)
__global__ __launch_bounds__(NT_THREADS, 2)
void tc_gemm_sc(const __half* __restrict__ A, const __half* __restrict__ B,
                __half* __restrict__ Ph, float* __restrict__ Pf,
                const float* __restrict__ Sa, const float* __restrict__ Ta,
                const float* __restrict__ Sb, const float* __restrict__ Tb,
                const float* __restrict__ gw)
{
    extern __shared__ char smem[];
    const long z = blockIdx.z;
    gemm_core<1>(A + z * (long)SS * DD + (size_t)blockIdx.y * BM * DD,
                 B + z * (long)SS * DD + (size_t)blockIdx.x * BN * DD,
                 nullptr, Ph + z * (long)SS * SS,
                 nullptr, CLS_SCALE, DD, SS,
                 blockIdx.y * BM, blockIdx.x * BN, smem,
                 Sa + z * SS, Ta + z * SS, Sb + z * SS, Tb + z * SS,
                 gw + z * SS, Pf + z * (long)SS * SS, nullptr);
}

// batched final GEMM with row-scaled output (EPI2)
__global__ __launch_bounds__(NT_THREADS, 2)
void tc_gemm_fin(const __half* __restrict__ A, const __half* __restrict__ B,
                 float* __restrict__ Cf, const float* __restrict__ bias,
                 const float* __restrict__ rs)
{
    extern __shared__ char smem[];
    const long z = blockIdx.z;
    gemm_core<2>(A + z * (long)SS * SS + (size_t)blockIdx.y * BM * SS,
                 B + z * (long)DD * SS + (size_t)blockIdx.x * BN * SS,
                 Cf + z * (long)SS * DD, nullptr,
                 bias, 1.0f, SS, DD,
                 blockIdx.y * BM, blockIdx.x * BN, smem,
                 nullptr, nullptr, nullptr, nullptr, nullptr, nullptr,
                 rs + z * SS);
}

// ---------------- row sums ----------------
__global__ void rowsum_kernel()
{
    const int row  = blockIdx.x * 8 + (threadIdx.x >> 5);
    const int lane = threadIdx.x & 31;
    const float4* pr = (const float4*)(g_SC + (size_t)row * SS);
    float s = 0.f;
    #pragma unroll
    for (int i = 0; i < 8; i++) {
        float4 v = pr[lane + 32 * i];
        s += v.x + v.y + v.z + v.w;
    }
    #pragma unroll
    for (int o = 16; o > 0; o >>= 1) s += __shfl_xor_sync(0xffffffffu, s, o);
    if (lane == 0) g_rsum[row] = 1.0f / s;
}

// ---------------- attn output: attn = p32 * inv ----------------
__global__ __launch_bounds__(256)
void attn_write_kernel(float* __restrict__ attn)
{
    const int row = blockIdx.x;
    const int j0 = threadIdx.x * 4;
    const float inv = g_rsum[row];
    float4 v = *(const float4*)&g_SC[(size_t)row * SS + j0];
    v.x *= inv; v.y *= inv; v.z *= inv; v.w *= inv;
    *(float4*)&attn[(size_t)row * SS + j0] = v;
}

// ---------------- fused q/k/v conversion + row stats ----------------
__global__ __launch_bounds__(256)
void conv_qkv_kernel(const float* __restrict__ q, const float* __restrict__ k,
                     const float* __restrict__ v,
                     __half* __restrict__ qh, __half* __restrict__ kh,
                     __half* __restrict__ vh)
{
    const int which = blockIdx.y;
    const float* src = (which == 0) ? q : (which == 1) ? k : v;
    __half* dst      = (which == 0) ? qh : (which == 1) ? kh : vh;

    int i = (blockIdx.x * blockDim.x + threadIdx.x) * 8;
    float4 v0 = *(const float4*)(src + i);
    float4 v1 = *(const float4*)(src + i + 4);
    float x[8] = {v0.x, v0.y, v0.z, v0.w, v1.x, v1.y, v1.z, v1.w};
    union { uint4 qd; __half b[8]; } H;
    #pragma unroll
    for (int j = 0; j < 8; j++) H.b[j] = __float2half(x[j]);
    *(uint4*)(dst + i) = H.qd;

    if (which < 2 && (i & (DD - 1)) == 0) {
        float s = 0.f, t = 0.f;
        #pragma unroll
        for (int m = 0; m < NQ; m++) {
            float tv = tanhf(x[m]);
            float a = expf(tv);
            s += a; t += a * tv;
        }
        int row = i >> 10;
        if (which == 0) { g_Sa[row] = s; g_Ta[row] = t; }
        else            { g_Sb[row] = s; g_Tb[row] = t; }
    }
}

// ---------------- weight conversion + fused cvec partials ----------------
__global__ void conv_w4_kernel(const float* __restrict__ wq, const float* __restrict__ wk,
                               const float* __restrict__ wv, const float* __restrict__ wo,
                               const float* __restrict__ bq)
{
    const int which = blockIdx.z;
    __shared__ float tile[32][33];
    __shared__ float red[8][32];
    const int tx = threadIdx.x, ty = threadIdx.y;
    if (which < 3) {
        const float* src = (which == 0) ? wq : (which == 1) ? wk : wv;
        __half* dst = (__half*)g_wT[which];
        const int x = blockIdx.x * 32 + tx;
        const int y0 = blockIdx.y * 32;
        #pragma unroll
        for (int i = ty; i < 32; i += 8)
            tile[i][tx] = src[(size_t)(y0 + i) * DD + x];
        __syncthreads();
        #pragma unroll
        for (int i = ty; i < 32; i += 8)
            dst[(size_t)(blockIdx.x * 32 + i) * DD + y0 + tx] = __float2half(tile[tx][i]);
        if (which == 1) {
            float p = 0.f;
            #pragma unroll
            for (int i = 0; i < 4; i++)
                p += bq[y0 + ty * 4 + i] * tile[ty * 4 + i][tx];
            red[ty][tx] = p;
            __syncthreads();
            if (ty == 0) {
                float t = red[0][tx];
                #pragma unroll
                for (int w = 1; w < 8; w++) t += red[w][tx];
                g_cpart[blockIdx.y * DD + x] = t;
            }
        }
    } else {
        __half* dst = (__half*)g_woh;
        const int x = blockIdx.x * 32 + tx;
        const int y0 = blockIdx.y * 32;
        #pragma unroll
        for (int i = ty; i < 32; i += 8) {
            size_t o = (size_t)(y0 + i) * DD + x;
            dst[o] = __float2half(wo[o]);
        }
    }
}

// ---------------- cvec reduction ----------------
__global__ void reduce_cvec_kernel()
{
    int d = blockIdx.x * 256 + threadIdx.x;
    float s = 0.f;
    #pragma unroll
    for (int j = 0; j < 32; j++) s += g_cpart[j * DD + d];
    g_cvec[d] = s;
}

// ---------------- gw / obias from fp16 copies ----------------
__global__ void gw_obias_kernel(const __half* __restrict__ kh, const __half* __restrict__ woh,
                                const float* __restrict__ bv, const float* __restrict__ bo)
{
    const int wid = threadIdx.x >> 5, lane = threadIdx.x & 31;
    const int row = blockIdx.x * 8 + wid;
    if (blockIdx.y == 0) {
        const __half2* mr = (const __half2*)(kh + (size_t)row * DD);
        const float2* cv = (const float2*)g_cvec;
        float s = 0.f;
        #pragma unroll
        for (int m = 0; m < 16; m++) {
            int idx = lane + 32 * m;
            float2 f = __half22float2(mr[idx]);
            float2 c = cv[idx];
            s += f.x * c.x + f.y * c.y;
        }
        #pragma unroll
        for (int o = 16; o > 0; o >>= 1) s += __shfl_xor_sync(0xffffffffu, s, o);
        if (lane == 0) g_gw[row] = CLS_SCALE * s;
    } else {
        if (row >= DD) return;
        const __half2* wr = (const __half2*)(woh + (size_t)row * DD);
        const float2* bv2 = (const float2*)bv;
        float s = 0.f;
        #pragma unroll
        for (int m = 0; m < 16; m++) {
            int idx = lane + 32 * m;
            float2 f = __half22float2(wr[idx]);
            float2 c = bv2[idx];
            s += f.x * c.x + f.y * c.y;
        }
        #pragma unroll
        for (int o = 16; o > 0; o >>= 1) s += __shfl_xor_sync(0xffffffffu, s, o);
        if (lane == 0) g_obias[row] = s + bo[row];
    }
}

// ---------------- launcher (R13 shape; combined big GEMM, no transpose) ----------------
#define SYMF(ptr, sym) cudaGetSymbolAddress((void**)&ptr, sym)

static cudaStream_t g_s1 = nullptr, g_s2 = nullptr;
static cudaEvent_t  g_evRoot, g_evQKV, g_evW, g_evGW, g_evRS, g_evAW;
static bool g_inited = false;

extern "C" void kernel_launch(void* const* d_in, const int* in_sizes, int n_in,
                              void* d_out, int out_size)
{
    const float* query = (const float*)d_in[0];
    const float* key   = (const float*)d_in[1];
    const float* value = (const float*)d_in[2];
    const float* Wq    = (const float*)d_in[3];
    const float* bq    = (const float*)d_in[4];
    const float* Wk    = (const float*)d_in[5];
    const float* bk    = (const float*)d_in[6];
    const float* Wv    = (const float*)d_in[7];
    const float* bv    = (const float*)d_in[8];
    const float* Wo    = (const float*)d_in[9];
    const float* bo    = (const float*)d_in[10];
    float* out = (float*)d_out;
    (void)bk;

    __half *qh,*kh,*vh,*wTbase,*woh,*W1T,*Gm,*Th,*VOT,*Ph;
    float *SCp,*obias,*rsum,*Sa,*Ta,*Sb,*Tb,*gw;
    SYMF(qh,g_qh); SYMF(kh,g_kh); SYMF(vh,g_vh);
    SYMF(wTbase,g_wT); SYMF(woh,g_woh);
    SYMF(W1T,g_W1T); SYMF(Gm,g_G);
    SYMF(Th,g_Th); SYMF(VOT,g_VOT); SYMF(Ph,g_Ph);
    SYMF(SCp,g_SC); SYMF(obias,g_obias); SYMF(rsum,g_rsum);
    SYMF(Sa,g_Sa); SYMF(Ta,g_Ta); SYMF(Sb,g_Sb); SYMF(Tb,g_Tb); SYMF(gw,g_gw);
    __half* WqT = wTbase;
    __half* WkT = wTbase + (size_t)NW;
    __half* WvT = wTbase + (size_t)2*NW;

    const long OUT_N = (long)NM;
    float* attn_out = ((long)out_size >= 2 * OUT_N) ? (out + OUT_N) : nullptr;

    if (!g_inited) {
        cudaStreamCreateWithFlags(&g_s1, cudaStreamNonBlocking);
        cudaStreamCreateWithFlags(&g_s2, cudaStreamNonBlocking);
        cudaEventCreateWithFlags(&g_evRoot, cudaEventDisableTiming);
        cudaEventCreateWithFlags(&g_evQKV,  cudaEventDisableTiming);
        cudaEventCreateWithFlags(&g_evW,    cudaEventDisableTiming);
        cudaEventCreateWithFlags(&g_evGW,   cudaEventDisableTiming);
        cudaEventCreateWithFlags(&g_evRS,   cudaEventDisableTiming);
        cudaEventCreateWithFlags(&g_evAW,   cudaEventDisableTiming);
        cudaFuncSetAttribute(tc_gemm_dual, cudaFuncAttributeMaxDynamicSharedMemorySize, SMEM_GEMM);
        cudaFuncSetAttribute(tc_gemm_big,  cudaFuncAttributeMaxDynamicSharedMemorySize, SMEM_GEMM);
        cudaFuncSetAttribute(tc_gemm_sc,   cudaFuncAttributeMaxDynamicSharedMemorySize, SMEM_GEMM);
        cudaFuncSetAttribute(tc_gemm_fin,  cudaFuncAttributeMaxDynamicSharedMemorySize, SMEM_GEMM);
        g_inited = true;
    }
    cudaStream_t s0 = 0, s1 = g_s1, s2 = g_s2;

    // fork side streams
    cudaEventRecord(g_evRoot, s0);
    cudaStreamWaitEvent(s1, g_evRoot, 0);
    cudaStreamWaitEvent(s2, g_evRoot, 0);

    // s1: input path
    conv_qkv_kernel<<<dim3(NM/2048, 3), 256, 0, s1>>>(query, key, value, qh, kh, vh);
    cudaEventRecord(g_evQKV, s1);

    // s0: weight path (critical)
    conv_w4_kernel<<<dim3(32, 32, 4), dim3(32, 8), 0, s0>>>(Wq, Wk, Wv, Wo, bq);
    cudaEventRecord(g_evW, s0);
    tc_gemm_dual<<<dim3(8, 8, 2), NT_THREADS, SMEM_GEMM, s0>>>(WkT, WqT, W1T, woh, WvT, Gm, DD, DD);

    // s2: tables, cvec reduction, gw/obias
    build_tables_kernel<<<TBL_N/256, 256, 0, s2>>>();
    cudaStreamWaitEvent(s2, g_evW, 0);
    reduce_cvec_kernel<<<4, 256, 0, s2>>>();
    cudaStreamWaitEvent(s2, g_evQKV, 0);
    gw_obias_kernel<<<dim3(512, 2), 256, 0, s2>>>(kh, woh, bv, bo);
    cudaEventRecord(g_evGW, s2);

    // s0: combined big GEMM (512 CTAs): Th = q@W1T^T  and  VOT[b] = G@v[b]^T
    cudaStreamWaitEvent(s0, g_evQKV, 0);
    tc_gemm_big<<<dim3(8, 32, 2), NT_THREADS, SMEM_GEMM, s0>>>(qh, W1T, Th, Gm, vh, VOT);

    // s0: SC GEMM (fused quantum+exp; needs gw/tables)
    cudaStreamWaitEvent(s0, g_evGW, 0);
    tc_gemm_sc<<<dim3(8, 8, BB), NT_THREADS, SMEM_GEMM, s0>>>(Th, kh, Ph, SCp, Sa, Ta, Sb, Tb, gw);

    // s0: row sums
    rowsum_kernel<<<BSROWS/8, 256, 0, s0>>>();
    cudaEventRecord(g_evRS, s0);

    // s1: attn output (off critical path)
    if (attn_out) {
        cudaStreamWaitEvent(s1, g_evRS, 0);
        attn_write_kernel<<<BSROWS, 256, 0, s1>>>(attn_out);
        cudaEventRecord(g_evAW, s1);
    }

    // s0: final GEMM (row-scaled, + obias; VOT already ordered on s0)
    tc_gemm_fin<<<dim3(8, 8, BB), NT_THREADS, SMEM_GEMM, s0>>>(Ph, VOT, out, obias, rsum);

    if (attn_out) cudaStreamWaitEvent(s0, g_evAW, 0);
}

// round 17
// speedup vs baseline: 1.0258x; 1.0006x over previous
#include <cuda_runtime.h>
#include <cuda_fp16.h>
#include <math.h>
#include <stdint.h>

// ---------------- problem constants ----------------
#define BB 4
#define SS 1024
#define DD 1024
#define NQ 8
#define BSROWS (BB*SS)           // 4096
#define CLS_SCALE (0.7f/128.0f)  // ALPHA / (H*sqrt(HEAD_DIM))

#define NM (BSROWS*DD)           // 4,194,304
#define NW (DD*DD)               // 1,048,576

// ---------------- scratch (device globals) ----------------
__device__ uint4 g_qh[NM/8], g_kh[NM/8], g_vh[NM/8];
__device__ uint4 g_wT[3][NW/8];              // WqT, WkT, WvT (fp16, transposed)
__device__ uint4 g_woh[NW/8];                // Wo fp16 (row-major)
__device__ uint4 g_W1T[NW/8], g_G[NW/8];     // composed weights fp16
__device__ uint4 g_Th[NM/8], g_VOT[NM/8], g_Ph[NM/8];
__device__ float g_SC[NM];                   // unnormalized p (fp32)
__device__ float g_Sa[BSROWS], g_Ta[BSROWS], g_Sb[BSROWS], g_Tb[BSROWS];
__device__ float g_cpart[32*DD];
__device__ float g_cvec[DD];
__device__ float g_gw[BSROWS];
__device__ float g_obias[DD];
__device__ float g_rpart[8*BSROWS];          // per-coltile row partial sums of p
__device__ float g_rsum[BSROWS];             // 1 / row sum of p

// ---------------- lookup tables ----------------
#define TBL_N   4096
#define TBL_Z0  5.5f
#define TBL_Z1  44.0f
#define TBL_E0f (-16.0f)
#define TBL_E1f (16.0f)
__device__ float4 g_tblZ[TBL_N];   // (ln, dln, rcp, drcp)
__device__ float2 g_tblE[TBL_N];   // (exp, dexp)

__global__ void build_tables_kernel()
{
    int k = blockIdx.x * blockDim.x + threadIdx.x;
    if (k >= TBL_N) return;
    const float hz = (TBL_Z1 - TBL_Z0) / TBL_N;
    float z0 = TBL_Z0 + k * hz, z1 = z0 + hz;
    float l0 = logf(z0), l1 = logf(z1);
    float r0 = 1.0f / z0,  r1 = 1.0f / z1;
    g_tblZ[k] = make_float4(l0, (l1 - l0) / hz, r0, (r1 - r0) / hz);
    const float he = (TBL_E1f - TBL_E0f) / TBL_N;
    float x0 = TBL_E0f + k * he, x1 = x0 + he;
    float e0 = expf(x0), e1 = expf(x1);
    g_tblE[k] = make_float2(e0, (e1 - e0) / he);
}

// ---------------- PTX helpers ----------------
__device__ __forceinline__ uint32_t smem_u32(const void* p) {
    uint32_t a;
    asm("{ .reg .u64 t; cvta.to.shared.u64 t, %1; cvt.u32.u64 %0, t; }" : "=r"(a) : "l"(p));
    return a;
}
__device__ __forceinline__ void cp16(uint32_t dst, const void* src) {
    asm volatile("cp.async.cg.shared.global [%0], [%1], 16;" :: "r"(dst), "l"(src) : "memory");
}
__device__ __forceinline__ void cp_commit() { asm volatile("cp.async.commit_group;" ::: "memory"); }
template<int N>
__device__ __forceinline__ void cp_wait() { asm volatile("cp.async.wait_group %0;" :: "n"(N) : "memory"); }

__device__ __forceinline__ void ldsm4(uint32_t& r0, uint32_t& r1, uint32_t& r2, uint32_t& r3,
                                      uint32_t addr) {
    asm volatile("ldmatrix.sync.aligned.m8n8.x4.shared.b16 {%0,%1,%2,%3}, [%4];"
                 : "=r"(r0), "=r"(r1), "=r"(r2), "=r"(r3) : "r"(addr));
}
__device__ __forceinline__ void mma16816(float* c, const uint32_t* a, const uint32_t* b) {
    asm volatile("mma.sync.aligned.m16n8k16.row.col.f32.f16.f16.f32 "
                 "{%0,%1,%2,%3}, {%4,%5,%6,%7}, {%8,%9}, {%0,%1,%2,%3};"
                 : "+f"(c[0]), "+f"(c[1]), "+f"(c[2]), "+f"(c[3])
                 : "r"(a[0]), "r"(a[1]), "r"(a[2]), "r"(a[3]), "r"(b[0]), "r"(b[1]));
}

// quantum + exp (table-driven)
__device__ __forceinline__ float quantum_exp(float x, float Sa_, float Ta_,
                                             float Sb_, float Tb_, float gw_)
{
    const float HZ = (TBL_Z1 - TBL_Z0) / TBL_N;
    const float INV_HZ = (float)TBL_N / (TBL_Z1 - TBL_Z0);
    const float HE = (TBL_E1f - TBL_E0f) / TBL_N;
    const float INV_HE = (float)TBL_N / (TBL_E1f - TBL_E0f);
    float Z = Sa_ + Sb_;
    float tz = (Z - TBL_Z0) * INV_HZ;
    int kk = (int)tz;
    float4 c4 = __ldg(&g_tblZ[kk]);
    float fz = (Z - TBL_Z0) - HZ * (float)kk;
    float lnZ = fmaf(c4.y, fz, c4.x);
    float rz  = fmaf(c4.w, fz, c4.z);
    float c = x + gw_ + 0.3f * (lnZ - (Ta_ + Tb_) * rz);
    float tx = (c - TBL_E0f) * INV_HE;
    tx = fminf(fmaxf(tx, 0.f), (float)(TBL_N - 1));
    int ke = (int)tx;
    float2 e2 = __ldg(&g_tblE[ke]);
    float fe = (c - TBL_E0f) - HE * (float)ke;
    return fmaf(e2.y, fe, e2.x);
}

// ---------------- fp16 HMMA GEMM core (templated epilogue) ----------------
#define BM 128
#define BN 128
#define BKK 64
#define NT_THREADS 256
#define OFF_B 16384
#define STAGE_BYTES 32768
#define NSTAGE 3
#define SMEM_GEMM (NSTAGE*STAGE_BYTES)

__device__ __forceinline__ void load_stage(
    uint32_t st, const __half* a, const __half* b, int K, int k0, int tid)
{
    #pragma unroll
    for (int i = 0; i < 4; i++) {
        int id = tid + i * 256;
        int r = id >> 3, c = id & 7;
        uint32_t off = (uint32_t)(r * 128 + ((c ^ (r & 7)) << 4));
        size_t ge = (size_t)r * K + k0 + c * 8;
        cp16(st + off,         a + ge);
        cp16(st + OFF_B + off, b + ge);
    }
}

template<int EPI>
__device__ __forceinline__ void gemm_core(
    const __half* __restrict__ a_p, const __half* __restrict__ b_p,
    float* __restrict__ Cf, __half* __restrict__ Ch,
    const float* __restrict__ bias, float scale, int K, int ldc,
    int row_base, int col_base, char* smem,
    const float* qSa, const float* qTa, const float* qSb, const float* qTb,
    const float* qgw, float* Pf, const float* rs, float* Prow)
{
    const uint32_t sbase = smem_u32(smem);
    const int tid  = threadIdx.x;
    const int lane = tid & 31;
    const int wid  = tid >> 5;
    const int warp_m = wid >> 2;
    const int warp_n = wid & 3;
    const int g = lane >> 3;
    const int r = lane & 7;

    float acc[4][4][4];
    #pragma unroll
    for (int i = 0; i < 4; i++)
        #pragma unroll
        for (int j = 0; j < 4; j++)
            #pragma unroll
            for (int q = 0; q < 4; q++) acc[i][j][q] = 0.f;

    const int NKB = K / BKK;

    load_stage(sbase, a_p, b_p, K, 0, tid);
    cp_commit();
    load_stage(sbase + STAGE_BYTES, a_p, b_p, K, BKK, tid);
    cp_commit();

    int sidx = 0;
    for (int kb = 0; kb < NKB; kb++) {
        if (kb + 1 < NKB) cp_wait<1>(); else cp_wait<0>();
        __syncthreads();

        if (kb + 2 < NKB) {
            int s2 = sidx + 2; if (s2 >= NSTAGE) s2 -= NSTAGE;
            load_stage(sbase + s2 * STAGE_BYTES, a_p, b_p, K, (kb + 2) * BKK, tid);
            cp_commit();
        }

        const uint32_t st = sbase + sidx * STAGE_BYTES;
        #pragma unroll
        for (int ks = 0; ks < 4; ks++) {
            uint32_t ah[4][4], bh[4][2];
            const int cA = ((2 * ks + (g >> 1)) ^ r) << 4;
            #pragma unroll
            for (int mi = 0; mi < 4; mi++) {
                uint32_t rowA = warp_m * 64 + mi * 16 + ((g & 1) << 3) + r;
                ldsm4(ah[mi][0], ah[mi][1], ah[mi][2], ah[mi][3], st + rowA * 128 + cA);
            }
            const int cB = ((2 * ks + (g & 1)) ^ r) << 4;
            #pragma unroll
            for (int p = 0; p < 2; p++) {
                uint32_t rowB = warp_n * 32 + ((2 * p + (g >> 1)) << 3) + r;
                uint32_t t0, t1, t2, t3;
                ldsm4(t0, t1, t2, t3, st + OFF_B + rowB * 128 + cB);
                bh[2*p][0] = t0; bh[2*p][1] = t1; bh[2*p+1][0] = t2; bh[2*p+1][1] = t3;
            }
            #pragma unroll
            for (int mi = 0; mi < 4; mi++)
                #pragma unroll
                for (int ni = 0; ni < 4; ni++)
                    mma16816(acc[mi][ni], ah[mi], bh[ni]);
        }
        sidx++; if (sidx >= NSTAGE) sidx = 0;
    }

    float psum[4][2];
    #pragma unroll
    for (int i = 0; i < 4; i++) { psum[i][0] = 0.f; psum[i][1] = 0.f; }

    #pragma unroll
    for (int mi = 0; mi < 4; mi++) {
        #pragma unroll
        for (int ni = 0; ni < 4; ni++) {
            const int row0 = row_base + warp_m * 64 + mi * 16 + (lane >> 2);
            const int col  = col_base + warp_n * 32 + ni * 8 + 2 * (lane & 3);
            #pragma unroll
            for (int h = 0; h < 2; h++) {
                float x0 = acc[mi][ni][2*h + 0] * scale;
                float x1 = acc[mi][ni][2*h + 1] * scale;
                const int row = row0 + 8*h;
                const size_t o = (size_t)row * ldc + col;
                if (EPI == 0) {
                    union { __half b[2]; uint32_t u; } H;
                    H.b[0] = __float2half(x0); H.b[1] = __float2half(x1);
                    *(uint32_t*)&Ch[o] = H.u;
                } else if (EPI == 1) {
                    float Sa_ = __ldg(qSa + row), Ta_ = __ldg(qTa + row);
                    float p0 = quantum_exp(x0, Sa_, Ta_, __ldg(qSb + col),
                                           __ldg(qTb + col), __ldg(qgw + col));
                    float p1 = quantum_exp(x1, Sa_, Ta_, __ldg(qSb + col + 1),
                                           __ldg(qTb + col + 1), __ldg(qgw + col + 1));
                    *(float2*)&Pf[o] = make_float2(p0, p1);
                    union { __half b[2]; uint32_t u; } H;
                    H.b[0] = __float2half(p0); H.b[1] = __float2half(p1);
                    *(uint32_t*)&Ch[o] = H.u;
                    psum[mi][h] += p0 + p1;
                } else {  // EPI == 2
                    float r_ = __ldg(rs + row);
                    float y0 = fmaf(x0, r_, __ldg(bias + col));
                    float y1 = fmaf(x1, r_, __ldg(bias + col + 1));
                    *(float2*)&Cf[o] = make_float2(y0, y1);
                }
            }
        }
    }

    if (EPI == 1) {
        // deterministic per-tile row sums -> Prow[row_base + localrow]
        #pragma unroll
        for (int mi = 0; mi < 4; mi++)
            #pragma unroll
            for (int h2 = 0; h2 < 2; h2++) {
                float s = psum[mi][h2];
                s += __shfl_xor_sync(0xffffffffu, s, 1);
                s += __shfl_xor_sync(0xffffffffu, s, 2);
                psum[mi][h2] = s;
            }
        float* red = (float*)smem;   // 4 warp_n slices x 128 rows
        __syncthreads();
        if ((lane & 3) == 0) {
            #pragma unroll
            for (int mi = 0; mi < 4; mi++)
                #pragma unroll
                for (int h2 = 0; h2 < 2; h2++) {
                    int lr = warp_m * 64 + mi * 16 + 8 * h2 + (lane >> 2);
                    red[warp_n * 128 + lr] = psum[mi][h2];
                }
        }
        __syncthreads();
        if (tid < 128)
            Prow[row_base + tid] = red[tid] + red[128 + tid] + red[256 + tid] + red[384 + tid];
    }
}

// dual NT GEMM (EPI0): small composed-weight pair
__global__ __launch_bounds__(NT_THREADS, 2)
void tc_gemm_dual(const __half* __restrict__ A0, const __half* __restrict__ B0, __half* __restrict__ C0,
                  const __half* __restrict__ A1, const __half* __restrict__ B1, __half* __restrict__ C1,
                  int K, int ldc)
{
    extern __shared__ char smem[];
    const __half* A = blockIdx.z ? A1 : A0;
    const __half* B = blockIdx.z ? B1 : B0;
    __half*       C = blockIdx.z ? C1 : C0;
    gemm_core<0>(A + (size_t)blockIdx.y * BM * K,
                 B + (size_t)blockIdx.x * BN * K,
                 nullptr, C, nullptr, 1.0f, K, ldc,
                 blockIdx.y * BM, blockIdx.x * BN, smem,
                 nullptr, nullptr, nullptr, nullptr, nullptr, nullptr, nullptr, nullptr);
}

// combined big GEMM (EPI0), grid (8,32,2):
//   z=0: Th = q @ W1T^T        (ldc=DD)
//   z=1: VOT[b] = G @ v[b]^T   (by = b*8 + tile, ldc=SS)
__global__ __launch_bounds__(NT_THREADS, 2)
void tc_gemm_big(const __half* __restrict__ qh, const __half* __restrict__ W1T,
                 __half* __restrict__ Th,
                 const __half* __restrict__ G, const __half* __restrict__ v,
                 __half* __restrict__ VOT)
{
    extern __shared__ char smem[];
    if (blockIdx.z == 0) {
        gemm_core<0>(qh + (size_t)blockIdx.y * BM * DD,
                     W1T + (size_t)blockIdx.x * BN * DD,
                     nullptr, Th, nullptr, 1.0f, DD, DD,
                     blockIdx.y * BM, blockIdx.x * BN, smem,
                     nullptr, nullptr, nullptr, nullptr, nullptr, nullptr, nullptr, nullptr);
    } else {
        const int b = blockIdx.y >> 3;
        const int yt = blockIdx.y & 7;
        gemm_core<0>(G + (size_t)yt * BM * DD,
                     v + (size_t)b * SS * DD + (size_t)blockIdx.x * BN * DD,
                     nullptr, VOT + (size_t)b * DD * SS, nullptr, 1.0f, DD, SS,
                     yt * BM, blockIdx.x * BN, smem,
                     nullptr, nullptr, nullptr, nullptr, nullptr, nullptr, nullptr, nullptr);
    }
}

// batched SC GEMM with fused quantum+exp + row-partial epilogue (EPI1)
__global__ __launch_bounds__(NT_THREADS, 2)
void tc_gemm_sc(const __half* __restrict__ A, const __half* __restrict__ B,
                __half* __restrict__ Ph, float* __restrict__ Pf,
                const float* __restrict__ Sa, const float* __restrict__ Ta,
                const float* __restrict__ Sb, const float* __restrict__ Tb,
                const float* __restrict__ gw, float* __restrict__ rpart)
{
    extern __shared__ char smem[];
    const long z = blockIdx.z;
    gemm_core<1>(A + z * (long)SS * DD + (size_t)blockIdx.y * BM * DD,
                 B + z * (long)SS * DD + (size_t)blockIdx.x * BN * DD,
                 nullptr, Ph + z * (long)SS * SS,
                 nullptr, CLS_SCALE, DD, SS,
                 blockIdx.y * BM, blockIdx.x * BN, smem,
                 Sa + z * SS, Ta + z * SS, Sb + z * SS, Tb + z * SS,
                 gw + z * SS, Pf + z * (long)SS * SS, nullptr,
                 rpart + (size_t)blockIdx.x * BSROWS + z * SS);
}

// batched final GEMM with row-scaled output (EPI2)
__global__ __launch_bounds__(NT_THREADS, 2)
void tc_gemm_fin(const __half* __restrict__ A, const __half* __restrict__ B,
                 float* __restrict__ Cf, const float* __restrict__ bias,
                 const float* __restrict__ rs)
{
    extern __shared__ char smem[];
    const long z = blockIdx.z;
    gemm_core<2>(A + z * (long)SS * SS + (size_t)blockIdx.y * BM * SS,
                 B + z * (long)DD * SS + (size_t)blockIdx.x * BN * SS,
                 Cf + z * (long)SS * DD, nullptr,
                 bias, 1.0f, SS, DD,
                 blockIdx.y * BM, blockIdx.x * BN, smem,
                 nullptr, nullptr, nullptr, nullptr, nullptr, nullptr,
                 rs + z * SS, nullptr);
}

// ---------------- rsum reduce: g_rsum[row] = 1 / sum_j g_rpart[j][row] ----------------
__global__ void rsum_reduce_kernel()
{
    int row = blockIdx.x * 256 + threadIdx.x;
    float s = 0.f;
    #pragma unroll
    for (int j = 0; j < 8; j++) s += g_rpart[j * BSROWS + row];
    g_rsum[row] = 1.0f / s;
}

// ---------------- attn output: attn = p32 * inv ----------------
__global__ __launch_bounds__(256)
void attn_write_kernel(float* __restrict__ attn)
{
    const int row = blockIdx.x;
    const int j0 = threadIdx.x * 4;
    const float inv = g_rsum[row];
    float4 v = *(const float4*)&g_SC[(size_t)row * SS + j0];
    v.x *= inv; v.y *= inv; v.z *= inv; v.w *= inv;
    *(float4*)&attn[(size_t)row * SS + j0] = v;
}

// ---------------- q/k/v conversion + row stats (split: mode0={q,v}, mode1={k}) ----------------
__global__ __launch_bounds__(256)
void conv_qkv_kernel(const float* __restrict__ q, const float* __restrict__ k,
                     const float* __restrict__ v,
                     __half* __restrict__ qh, __half* __restrict__ kh,
                     __half* __restrict__ vh, int mode)
{
    const int which = (mode == 0) ? (blockIdx.y == 0 ? 0 : 2) : 1;
    const float* src = (which == 0) ? q : (which == 1) ? k : v;
    __half* dst      = (which == 0) ? qh : (which == 1) ? kh : vh;

    int i = (blockIdx.x * blockDim.x + threadIdx.x) * 8;
    float4 v0 = *(const float4*)(src + i);
    float4 v1 = *(const float4*)(src + i + 4);
    float x[8] = {v0.x, v0.y, v0.z, v0.w, v1.x, v1.y, v1.z, v1.w};
    union { uint4 qd; __half b[8]; } H;
    #pragma unroll
    for (int j = 0; j < 8; j++) H.b[j] = __float2half(x[j]);
    *(uint4*)(dst + i) = H.qd;

    if (which < 2 && (i & (DD - 1)) == 0) {
        float s = 0.f, t = 0.f;
        #pragma unroll
        for (int m = 0; m < NQ; m++) {
            float tv = tanhf(x[m]);
            float a = expf(tv);
            s += a; t += a * tv;
        }
        int row = i >> 10;
        if (which == 0) { g_Sa[row] = s; g_Ta[row] = t; }
        else            { g_Sb[row] = s; g_Tb[row] = t; }
    }
}

// ---------------- weight conversion + fused cvec partials ----------------
__global__ void conv_w4_kernel(const float* __restrict__ wq, const float* __restrict__ wk,
                               const float* __restrict__ wv, const float* __restrict__ wo,
                               const float* __restrict__ bq)
{
    const int which = blockIdx.z;
    __shared__ float tile[32][33];
    __shared__ float red[8][32];
    const int tx = threadIdx.x, ty = threadIdx.y;
    if (which < 3) {
        const float* src = (which == 0) ? wq : (which == 1) ? wk : wv;
        __half* dst = (__half*)g_wT[which];
        const int x = blockIdx.x * 32 + tx;
        const int y0 = blockIdx.y * 32;
        #pragma unroll
        for (int i = ty; i < 32; i += 8)
            tile[i][tx] = src[(size_t)(y0 + i) * DD + x];
        __syncthreads();
        #pragma unroll
        for (int i = ty; i < 32; i += 8)
            dst[(size_t)(blockIdx.x * 32 + i) * DD + y0 + tx] = __float2half(tile[tx][i]);
        if (which == 1) {
            float p = 0.f;
            #pragma unroll
            for (int i = 0; i < 4; i++)
                p += bq[y0 + ty * 4 + i] * tile[ty * 4 + i][tx];
            red[ty][tx] = p;
            __syncthreads();
            if (ty == 0) {
                float t = red[0][tx];
                #pragma unroll
                for (int w = 1; w < 8; w++) t += red[w][tx];
                g_cpart[blockIdx.y * DD + x] = t;
            }
        }
    } else {
        __half* dst = (__half*)g_woh;
        const int x = blockIdx.x * 32 + tx;
        const int y0 = blockIdx.y * 32;
        #pragma unroll
        for (int i = ty; i < 32; i += 8) {
            size_t o = (size_t)(y0 + i) * DD + x;
            dst[o] = __float2half(wo[o]);
        }
    }
}

// ---------------- cvec reduction ----------------
__global__ void reduce_cvec_kernel()
{
    int d = blockIdx.x * 256 + threadIdx.x;
    float s = 0.f;
    #pragma unroll
    for (int j = 0; j < 32; j++) s += g_cpart[j * DD + d];
    g_cvec[d] = s;
}

// ---------------- gw / obias from fp16 copies ----------------
__global__ void gw_obias_kernel(const __half* __restrict__ kh, const __half* __restrict__ woh,
                                const float* __restrict__ bv, const float* __restrict__ bo)
{
    const int wid = threadIdx.x >> 5, lane = threadIdx.x & 31;
    const int row = blockIdx.x * 8 + wid;
    if (blockIdx.y == 0) {
        const __half2* mr = (const __half2*)(kh + (size_t)row * DD);
        const float2* cv = (const float2*)g_cvec;
        float s = 0.f;
        #pragma unroll
        for (int m = 0; m < 16; m++) {
            int idx = lane + 32 * m;
            float2 f = __half22float2(mr[idx]);
            float2 c = cv[idx];
            s += f.x * c.x + f.y * c.y;
        }
        #pragma unroll
        for (int o = 16; o > 0; o >>= 1) s += __shfl_xor_sync(0xffffffffu, s, o);
        if (lane == 0) g_gw[row] = CLS_SCALE * s;
    } else {
        if (row >= DD) return;
        const __half2* wr = (const __half2*)(woh + (size_t)row * DD);
        const float2* bv2 = (const float2*)bv;
        float s = 0.f;
        #pragma unroll
        for (int m = 0; m < 16; m++) {
            int idx = lane + 32 * m;
            float2 f = __half22float2(wr[idx]);
            float2 c = bv2[idx];
            s += f.x * c.x + f.y * c.y;
        }
        #pragma unroll
        for (int o = 16; o > 0; o >>= 1) s += __shfl_xor_sync(0xffffffffu, s, o);
        if (lane == 0) g_obias[row] = s + bo[row];
    }
}

// ---------------- launcher ----------------
#define SYMF(ptr, sym) cudaGetSymbolAddress((void**)&ptr, sym)

static cudaStream_t g_s1 = nullptr, g_s2 = nullptr;
static cudaEvent_t  g_evRoot, g_evQV, g_evK, g_evW, g_evGW, g_evRS, g_evAW;
static bool g_inited = false;

extern "C" void kernel_launch(void* const* d_in, const int* in_sizes, int n_in,
                              void* d_out, int out_size)
{
    const float* query = (const float*)d_in[0];
    const float* key   = (const float*)d_in[1];
    const float* value = (const float*)d_in[2];
    const float* Wq    = (const float*)d_in[3];
    const float* bq    = (const float*)d_in[4];
    const float* Wk    = (const float*)d_in[5];
    const float* bk    = (const float*)d_in[6];
    const float* Wv    = (const float*)d_in[7];
    const float* bv    = (const float*)d_in[8];
    const float* Wo    = (const float*)d_in[9];
    const float* bo    = (const float*)d_in[10];
    float* out = (float*)d_out;
    (void)bk;

    __half *qh,*kh,*vh,*wTbase,*woh,*W1T,*Gm,*Th,*VOT,*Ph;
    float *SCp,*obias,*rsum,*rpart,*Sa,*Ta,*Sb,*Tb,*gw;
    SYMF(qh,g_qh); SYMF(kh,g_kh); SYMF(vh,g_vh);
    SYMF(wTbase,g_wT); SYMF(woh,g_woh);
    SYMF(W1T,g_W1T); SYMF(Gm,g_G);
    SYMF(Th,g_Th); SYMF(VOT,g_VOT); SYMF(Ph,g_Ph);
    SYMF(SCp,g_SC); SYMF(obias,g_obias); SYMF(rsum,g_rsum); SYMF(rpart,g_rpart);
    SYMF(Sa,g_Sa); SYMF(Ta,g_Ta); SYMF(Sb,g_Sb); SYMF(Tb,g_Tb); SYMF(gw,g_gw);
    __half* WqT = wTbase;
    __half* WkT = wTbase + (size_t)NW;
    __half* WvT = wTbase + (size_t)2*NW;

    const long OUT_N = (long)NM;
    float* attn_out = ((long)out_size >= 2 * OUT_N) ? (out + OUT_N) : nullptr;

    if (!g_inited) {
        cudaStreamCreateWithFlags(&g_s1, cudaStreamNonBlocking);
        cudaStreamCreateWithFlags(&g_s2, cudaStreamNonBlocking);
        cudaEventCreateWithFlags(&g_evRoot, cudaEventDisableTiming);
        cudaEventCreateWithFlags(&g_evQV,   cudaEventDisableTiming);
        cudaEventCreateWithFlags(&g_evK,    cudaEventDisableTiming);
        cudaEventCreateWithFlags(&g_evW,    cudaEventDisableTiming);
        cudaEventCreateWithFlags(&g_evGW,   cudaEventDisableTiming);
        cudaEventCreateWithFlags(&g_evRS,   cudaEventDisableTiming);
        cudaEventCreateWithFlags(&g_evAW,   cudaEventDisableTiming);
        cudaFuncSetAttribute(tc_gemm_dual, cudaFuncAttributeMaxDynamicSharedMemorySize, SMEM_GEMM);
        cudaFuncSetAttribute(tc_gemm_big,  cudaFuncAttributeMaxDynamicSharedMemorySize, SMEM_GEMM);
        cudaFuncSetAttribute(tc_gemm_sc,   cudaFuncAttributeMaxDynamicSharedMemorySize, SMEM_GEMM);
        cudaFuncSetAttribute(tc_gemm_fin,  cudaFuncAttributeMaxDynamicSharedMemorySize, SMEM_GEMM);
        g_inited = true;
    }
    cudaStream_t s0 = 0, s1 = g_s1, s2 = g_s2;

    // fork side streams
    cudaEventRecord(g_evRoot, s0);
    cudaStreamWaitEvent(s1, g_evRoot, 0);
    cudaStreamWaitEvent(s2, g_evRoot, 0);

    // s1: q+v conversion first (gates big), then k (gates SC path)
    conv_qkv_kernel<<<dim3(NM/2048, 2), 256, 0, s1>>>(query, key, value, qh, kh, vh, 0);
    cudaEventRecord(g_evQV, s1);
    conv_qkv_kernel<<<dim3(NM/2048, 1), 256, 0, s1>>>(query, key, value, qh, kh, vh, 1);
    cudaEventRecord(g_evK, s1);

    // s0: weight path (critical)
    conv_w4_kernel<<<dim3(32, 32, 4), dim3(32, 8), 0, s0>>>(Wq, Wk, Wv, Wo, bq);
    cudaEventRecord(g_evW, s0);
    tc_gemm_dual<<<dim3(8, 8, 2), NT_THREADS, SMEM_GEMM, s0>>>(WkT, WqT, W1T, woh, WvT, Gm, DD, DD);

    // s2: tables, cvec reduction, gw/obias (needs kh)
    build_tables_kernel<<<TBL_N/256, 256, 0, s2>>>();
    cudaStreamWaitEvent(s2, g_evW, 0);
    reduce_cvec_kernel<<<4, 256, 0, s2>>>();
    cudaStreamWaitEvent(s2, g_evK, 0);
    gw_obias_kernel<<<dim3(512, 2), 256, 0, s2>>>(kh, woh, bv, bo);
    cudaEventRecord(g_evGW, s2);

    // s0: combined big GEMM (needs qh, vh only)
    cudaStreamWaitEvent(s0, g_evQV, 0);
    tc_gemm_big<<<dim3(8, 32, 2), NT_THREADS, SMEM_GEMM, s0>>>(qh, W1T, Th, Gm, vh, VOT);

    // s0: SC GEMM (fused quantum+exp + row partials; evGW implies evK)
    cudaStreamWaitEvent(s0, g_evGW, 0);
    tc_gemm_sc<<<dim3(8, 8, BB), NT_THREADS, SMEM_GEMM, s0>>>(Th, kh, Ph, SCp, Sa, Ta, Sb, Tb, gw, rpart);

    // s0: tiny rsum reduce (replaces 16MB rowsum re-read)
    rsum_reduce_kernel<<<BSROWS/256, 256, 0, s0>>>();
    cudaEventRecord(g_evRS, s0);

    // s1: attn output (off critical path)
    if (attn_out) {
        cudaStreamWaitEvent(s1, g_evRS, 0);
        attn_write_kernel<<<BSROWS, 256, 0, s1>>>(attn_out);
        cudaEventRecord(g_evAW, s1);
    }

    // s0: final GEMM (row-scaled, + obias)
    tc_gemm_fin<<<dim3(8, 8, BB), NT_THREADS, SMEM_GEMM, s0>>>(Ph, VOT, out, obias, rsum);

    if (attn_out) cudaStreamWaitEvent(s0, g_evAW, 0);
}